// round 1
// baseline (speedup 1.0000x reference)
#include <cuda_runtime.h>

#define N_CTX 4096
#define D_MODEL 2048

// Scratch (allocation-free: static device globals).
__device__ float g_buf1[(size_t)N_CTX * D_MODEL];     // 32 MB: q, then attn@E
__device__ float g_scores[(size_t)N_CTX * N_CTX];     // 64 MB: scores / attn

// ---------------------------------------------------------------------------
// SGEMM NN: C[M,N] = A[M,K] @ B[K,N], all row-major.
// Assumes M%128==0, N%128==0, K%8==0, rows 16B-aligned (K%4==0, N%4==0).
// CAUSAL_K: truncate the k-loop at the end of this block-row (valid when A is
// a causal attention matrix whose entries above the diagonal are zero).
// ---------------------------------------------------------------------------
template <bool CAUSAL_K>
__global__ __launch_bounds__(256) void sgemm_nn(
    const float* __restrict__ A, const float* __restrict__ B,
    float* __restrict__ C, int M, int N, int K)
{
    constexpr int BM = 128, BN = 128, BK = 8;
    __shared__ float As[BK][BM];
    __shared__ float Bs[BK][BN];

    const int bx = blockIdx.x, by = blockIdx.y;
    const int t  = threadIdx.x;          // 0..255
    const int tx = t & 15;               // 0..15 -> 8 cols each
    const int ty = t >> 4;               // 0..15 -> 8 rows each
    const int rowBase = by * BM;
    const int colBase = bx * BN;
    const int kEnd = CAUSAL_K ? min(K, (by + 1) * BM) : K;

    // A-tile load mapping: 128x8 tile, one float4 per thread
    const int aRow = t >> 1;             // 0..127
    const int aCol = (t & 1) * 4;        // 0 or 4
    // B-tile load mapping: 8x128 tile, one float4 per thread
    const int bRow = t >> 5;             // 0..7
    const int bCol = (t & 31) * 4;       // 0..124

    float acc[8][8] = {};

    for (int k0 = 0; k0 < kEnd; k0 += BK) {
        float4 a = *reinterpret_cast<const float4*>(
            A + (size_t)(rowBase + aRow) * K + k0 + aCol);
        As[aCol + 0][aRow] = a.x;
        As[aCol + 1][aRow] = a.y;
        As[aCol + 2][aRow] = a.z;
        As[aCol + 3][aRow] = a.w;
        float4 b = *reinterpret_cast<const float4*>(
            B + (size_t)(k0 + bRow) * N + colBase + bCol);
        *reinterpret_cast<float4*>(&Bs[bRow][bCol]) = b;
        __syncthreads();

        #pragma unroll
        for (int k = 0; k < BK; k++) {
            float af[8], bf[8];
            #pragma unroll
            for (int m = 0; m < 8; m++) af[m] = As[k][ty * 8 + m];
            #pragma unroll
            for (int n = 0; n < 8; n++) bf[n] = Bs[k][tx * 8 + n];
            #pragma unroll
            for (int m = 0; m < 8; m++)
                #pragma unroll
                for (int n = 0; n < 8; n++)
                    acc[m][n] = fmaf(af[m], bf[n], acc[m][n]);
        }
        __syncthreads();
    }

    #pragma unroll
    for (int m = 0; m < 8; m++) {
        float* crow = C + (size_t)(rowBase + ty * 8 + m) * N + colBase + tx * 8;
        #pragma unroll
        for (int n = 0; n < 8; n += 4) {
            float4 v = make_float4(acc[m][n], acc[m][n + 1], acc[m][n + 2], acc[m][n + 3]);
            *reinterpret_cast<float4*>(crow + n) = v;
        }
    }
}

// ---------------------------------------------------------------------------
// SGEMM NT: C[M,N] = A[M,K] @ B[N,K]^T, row-major. Causal: skip blocks
// strictly above the diagonal (bx > by) — softmax never reads them.
// ---------------------------------------------------------------------------
__global__ __launch_bounds__(256) void sgemm_nt_causal(
    const float* __restrict__ A, const float* __restrict__ B,
    float* __restrict__ C, int M, int N, int K)
{
    constexpr int BM = 128, BN = 128, BK = 8;
    const int bx = blockIdx.x, by = blockIdx.y;
    if (bx > by) return;  // strictly-upper block: never consumed

    __shared__ float As[BK][BM];
    __shared__ float Bs[BK][BN];

    const int t  = threadIdx.x;
    const int tx = t & 15;
    const int ty = t >> 4;
    const int rowBase = by * BM;
    const int colBase = bx * BN;

    const int aRow = t >> 1;
    const int aCol = (t & 1) * 4;
    // B is [N,K] row-major; load along K (contiguous), scatter-transpose into Bs
    const int bRowN = t >> 1;            // 0..127 (n within tile)
    const int bColK = (t & 1) * 4;       // 0 or 4 (k within tile)

    float acc[8][8] = {};

    for (int k0 = 0; k0 < K; k0 += BK) {
        float4 a = *reinterpret_cast<const float4*>(
            A + (size_t)(rowBase + aRow) * K + k0 + aCol);
        As[aCol + 0][aRow] = a.x;
        As[aCol + 1][aRow] = a.y;
        As[aCol + 2][aRow] = a.z;
        As[aCol + 3][aRow] = a.w;
        float4 b = *reinterpret_cast<const float4*>(
            B + (size_t)(colBase + bRowN) * K + k0 + bColK);
        Bs[bColK + 0][bRowN] = b.x;
        Bs[bColK + 1][bRowN] = b.y;
        Bs[bColK + 2][bRowN] = b.z;
        Bs[bColK + 3][bRowN] = b.w;
        __syncthreads();

        #pragma unroll
        for (int k = 0; k < BK; k++) {
            float af[8], bf[8];
            #pragma unroll
            for (int m = 0; m < 8; m++) af[m] = As[k][ty * 8 + m];
            #pragma unroll
            for (int n = 0; n < 8; n++) bf[n] = Bs[k][tx * 8 + n];
            #pragma unroll
            for (int m = 0; m < 8; m++)
                #pragma unroll
                for (int n = 0; n < 8; n++)
                    acc[m][n] = fmaf(af[m], bf[n], acc[m][n]);
        }
        __syncthreads();
    }

    #pragma unroll
    for (int m = 0; m < 8; m++) {
        float* crow = C + (size_t)(rowBase + ty * 8 + m) * N + colBase + tx * 8;
        #pragma unroll
        for (int n = 0; n < 8; n += 4) {
            float4 v = make_float4(acc[m][n], acc[m][n + 1], acc[m][n + 2], acc[m][n + 3]);
            *reinterpret_cast<float4*>(crow + n) = v;
        }
    }
}

// ---------------------------------------------------------------------------
// Causal softmax over row i (valid entries j <= i); writes zeros for j > i so
// downstream GEMM can run a truncated dense k-loop.
// ---------------------------------------------------------------------------
__global__ __launch_bounds__(256) void softmax_causal(float* __restrict__ s)
{
    const int i = blockIdx.x;
    float* row = s + (size_t)i * N_CTX;
    const int n = i + 1;
    const int t = threadIdx.x;
    __shared__ float red[256];

    float m = -3.0e38f;
    for (int j = t; j < n; j += 256) m = fmaxf(m, row[j]);
    red[t] = m;
    __syncthreads();
    for (int s2 = 128; s2 > 0; s2 >>= 1) {
        if (t < s2) red[t] = fmaxf(red[t], red[t + s2]);
        __syncthreads();
    }
    m = red[0];
    __syncthreads();

    float sum = 0.f;
    for (int j = t; j < n; j += 256) sum += expf(row[j] - m);
    red[t] = sum;
    __syncthreads();
    for (int s2 = 128; s2 > 0; s2 >>= 1) {
        if (t < s2) red[t] += red[t + s2];
        __syncthreads();
    }
    const float inv = 1.0f / red[0];

    for (int j = t; j < N_CTX; j += 256)
        row[j] = (j < n) ? expf(row[j] - m) * inv : 0.0f;
}

// ---------------------------------------------------------------------------
extern "C" void kernel_launch(void* const* d_in, const int* in_sizes, int n_in,
                              void* d_out, int out_size)
{
    const float* emb = (const float*)d_in[0];   // [4096, 2048]
    const float* qk  = (const float*)d_in[1];   // [2048, 2048]
    const float* ov  = (const float*)d_in[2];   // [2048, 2048]
    float* out = (float*)d_out;                 // [4096, 2048]

    float *buf1, *scores;
    cudaGetSymbolAddress((void**)&buf1, g_buf1);
    cudaGetSymbolAddress((void**)&scores, g_scores);

    dim3 blk(256);

    // 1) q = emb @ qk           [4096, 2048]
    sgemm_nn<false><<<dim3(D_MODEL / 128, N_CTX / 128), blk>>>(
        emb, qk, buf1, N_CTX, D_MODEL, D_MODEL);

    // 2) scores = q @ emb^T     [4096, 4096], lower-triangular blocks only
    sgemm_nt_causal<<<dim3(N_CTX / 128, N_CTX / 128), blk>>>(
        buf1, emb, scores, N_CTX, N_CTX, D_MODEL);

    // 3) attn = causal softmax(scores), zeros above diagonal
    softmax_causal<<<N_CTX, blk>>>(scores);

    // 4) ctx = attn @ emb       [4096, 2048], k-loop truncated at diagonal
    sgemm_nn<true><<<dim3(D_MODEL / 128, N_CTX / 128), blk>>>(
        scores, emb, buf1, N_CTX, D_MODEL, N_CTX);

    // 5) out = ctx @ ov         [4096, 2048]
    sgemm_nn<false><<<dim3(D_MODEL / 128, N_CTX / 128), blk>>>(
        buf1, ov, out, N_CTX, D_MODEL, D_MODEL);
}

// round 2
// speedup vs baseline: 1.0010x; 1.0010x over previous
#include <cuda_runtime.h>

#define N_CTX 4096
#define D_MODEL 2048

// Scratch (allocation-free: static device globals).
__device__ float g_buf1[(size_t)N_CTX * D_MODEL];     // 32 MB: q, then attn@E
__device__ float g_scores[(size_t)N_CTX * N_CTX];     // 64 MB: scores / attn

// ---------------------------------------------------------------------------
// SGEMM NN: C[M,N] = A[M,K] @ B[K,N], all row-major.
// Assumes M%128==0, N%128==0, K%8==0, rows 16B-aligned (K%4==0, N%4==0).
// CAUSAL_K: truncate the k-loop at the end of this block-row (valid when A is
// a causal attention matrix whose entries above the diagonal are zero).
// ---------------------------------------------------------------------------
template <bool CAUSAL_K>
__global__ __launch_bounds__(256) void sgemm_nn(
    const float* __restrict__ A, const float* __restrict__ B,
    float* __restrict__ C, int M, int N, int K)
{
    constexpr int BM = 128, BN = 128, BK = 8;
    __shared__ float As[BK][BM];
    __shared__ float Bs[BK][BN];

    const int bx = blockIdx.x, by = blockIdx.y;
    const int t  = threadIdx.x;          // 0..255
    const int tx = t & 15;               // 0..15 -> 8 cols each
    const int ty = t >> 4;               // 0..15 -> 8 rows each
    const int rowBase = by * BM;
    const int colBase = bx * BN;
    const int kEnd = CAUSAL_K ? min(K, (by + 1) * BM) : K;

    // A-tile load mapping: 128x8 tile, one float4 per thread
    const int aRow = t >> 1;             // 0..127
    const int aCol = (t & 1) * 4;        // 0 or 4
    // B-tile load mapping: 8x128 tile, one float4 per thread
    const int bRow = t >> 5;             // 0..7
    const int bCol = (t & 31) * 4;       // 0..124

    float acc[8][8] = {};

    for (int k0 = 0; k0 < kEnd; k0 += BK) {
        float4 a = *reinterpret_cast<const float4*>(
            A + (size_t)(rowBase + aRow) * K + k0 + aCol);
        As[aCol + 0][aRow] = a.x;
        As[aCol + 1][aRow] = a.y;
        As[aCol + 2][aRow] = a.z;
        As[aCol + 3][aRow] = a.w;
        float4 b = *reinterpret_cast<const float4*>(
            B + (size_t)(k0 + bRow) * N + colBase + bCol);
        *reinterpret_cast<float4*>(&Bs[bRow][bCol]) = b;
        __syncthreads();

        #pragma unroll
        for (int k = 0; k < BK; k++) {
            float af[8], bf[8];
            #pragma unroll
            for (int m = 0; m < 8; m++) af[m] = As[k][ty * 8 + m];
            #pragma unroll
            for (int n = 0; n < 8; n++) bf[n] = Bs[k][tx * 8 + n];
            #pragma unroll
            for (int m = 0; m < 8; m++)
                #pragma unroll
                for (int n = 0; n < 8; n++)
                    acc[m][n] = fmaf(af[m], bf[n], acc[m][n]);
        }
        __syncthreads();
    }

    #pragma unroll
    for (int m = 0; m < 8; m++) {
        float* crow = C + (size_t)(rowBase + ty * 8 + m) * N + colBase + tx * 8;
        #pragma unroll
        for (int n = 0; n < 8; n += 4) {
            float4 v = make_float4(acc[m][n], acc[m][n + 1], acc[m][n + 2], acc[m][n + 3]);
            *reinterpret_cast<float4*>(crow + n) = v;
        }
    }
}

// ---------------------------------------------------------------------------
// SGEMM NT: C[M,N] = A[M,K] @ B[N,K]^T, row-major. Causal: skip blocks
// strictly above the diagonal (bx > by) — softmax never reads them.
// ---------------------------------------------------------------------------
__global__ __launch_bounds__(256) void sgemm_nt_causal(
    const float* __restrict__ A, const float* __restrict__ B,
    float* __restrict__ C, int M, int N, int K)
{
    constexpr int BM = 128, BN = 128, BK = 8;
    const int bx = blockIdx.x, by = blockIdx.y;
    if (bx > by) return;  // strictly-upper block: never consumed

    __shared__ float As[BK][BM];
    __shared__ float Bs[BK][BN];

    const int t  = threadIdx.x;
    const int tx = t & 15;
    const int ty = t >> 4;
    const int rowBase = by * BM;
    const int colBase = bx * BN;

    const int aRow = t >> 1;
    const int aCol = (t & 1) * 4;
    // B is [N,K] row-major; load along K (contiguous), scatter-transpose into Bs
    const int bRowN = t >> 1;            // 0..127 (n within tile)
    const int bColK = (t & 1) * 4;       // 0 or 4 (k within tile)

    float acc[8][8] = {};

    for (int k0 = 0; k0 < K; k0 += BK) {
        float4 a = *reinterpret_cast<const float4*>(
            A + (size_t)(rowBase + aRow) * K + k0 + aCol);
        As[aCol + 0][aRow] = a.x;
        As[aCol + 1][aRow] = a.y;
        As[aCol + 2][aRow] = a.z;
        As[aCol + 3][aRow] = a.w;
        float4 b = *reinterpret_cast<const float4*>(
            B + (size_t)(colBase + bRowN) * K + k0 + bColK);
        Bs[bColK + 0][bRowN] = b.x;
        Bs[bColK + 1][bRowN] = b.y;
        Bs[bColK + 2][bRowN] = b.z;
        Bs[bColK + 3][bRowN] = b.w;
        __syncthreads();

        #pragma unroll
        for (int k = 0; k < BK; k++) {
            float af[8], bf[8];
            #pragma unroll
            for (int m = 0; m < 8; m++) af[m] = As[k][ty * 8 + m];
            #pragma unroll
            for (int n = 0; n < 8; n++) bf[n] = Bs[k][tx * 8 + n];
            #pragma unroll
            for (int m = 0; m < 8; m++)
                #pragma unroll
                for (int n = 0; n < 8; n++)
                    acc[m][n] = fmaf(af[m], bf[n], acc[m][n]);
        }
        __syncthreads();
    }

    #pragma unroll
    for (int m = 0; m < 8; m++) {
        float* crow = C + (size_t)(rowBase + ty * 8 + m) * N + colBase + tx * 8;
        #pragma unroll
        for (int n = 0; n < 8; n += 4) {
            float4 v = make_float4(acc[m][n], acc[m][n + 1], acc[m][n + 2], acc[m][n + 3]);
            *reinterpret_cast<float4*>(crow + n) = v;
        }
    }
}

// ---------------------------------------------------------------------------
// Causal softmax over row i (valid entries j <= i); writes zeros for j > i so
// downstream GEMM can run a truncated dense k-loop.
// ---------------------------------------------------------------------------
__global__ __launch_bounds__(256) void softmax_causal(float* __restrict__ s)
{
    const int i = blockIdx.x;
    float* row = s + (size_t)i * N_CTX;
    const int n = i + 1;
    const int t = threadIdx.x;
    __shared__ float red[256];

    float m = -3.0e38f;
    for (int j = t; j < n; j += 256) m = fmaxf(m, row[j]);
    red[t] = m;
    __syncthreads();
    for (int s2 = 128; s2 > 0; s2 >>= 1) {
        if (t < s2) red[t] = fmaxf(red[t], red[t + s2]);
        __syncthreads();
    }
    m = red[0];
    __syncthreads();

    float sum = 0.f;
    for (int j = t; j < n; j += 256) sum += expf(row[j] - m);
    red[t] = sum;
    __syncthreads();
    for (int s2 = 128; s2 > 0; s2 >>= 1) {
        if (t < s2) red[t] += red[t + s2];
        __syncthreads();
    }
    const float inv = 1.0f / red[0];

    for (int j = t; j < N_CTX; j += 256)
        row[j] = (j < n) ? expf(row[j] - m) * inv : 0.0f;
}

// ---------------------------------------------------------------------------
extern "C" void kernel_launch(void* const* d_in, const int* in_sizes, int n_in,
                              void* d_out, int out_size)
{
    const float* emb = (const float*)d_in[0];   // [4096, 2048]
    const float* qk  = (const float*)d_in[1];   // [2048, 2048]
    const float* ov  = (const float*)d_in[2];   // [2048, 2048]
    float* out = (float*)d_out;                 // [4096, 2048]

    float *buf1, *scores;
    cudaGetSymbolAddress((void**)&buf1, g_buf1);
    cudaGetSymbolAddress((void**)&scores, g_scores);

    dim3 blk(256);

    // 1) q = emb @ qk           [4096, 2048]
    sgemm_nn<false><<<dim3(D_MODEL / 128, N_CTX / 128), blk>>>(
        emb, qk, buf1, N_CTX, D_MODEL, D_MODEL);

    // 2) scores = q @ emb^T     [4096, 4096], lower-triangular blocks only
    sgemm_nt_causal<<<dim3(N_CTX / 128, N_CTX / 128), blk>>>(
        buf1, emb, scores, N_CTX, N_CTX, D_MODEL);

    // 3) attn = causal softmax(scores), zeros above diagonal
    softmax_causal<<<N_CTX, blk>>>(scores);

    // 4) ctx = attn @ emb       [4096, 2048], k-loop truncated at diagonal
    sgemm_nn<true><<<dim3(D_MODEL / 128, N_CTX / 128), blk>>>(
        scores, emb, buf1, N_CTX, D_MODEL, N_CTX);

    // 5) out = ctx @ ov         [4096, 2048]
    sgemm_nn<false><<<dim3(D_MODEL / 128, N_CTX / 128), blk>>>(
        buf1, ov, out, N_CTX, D_MODEL, D_MODEL);
}

// round 4
// speedup vs baseline: 2.1808x; 2.1787x over previous
#include <cuda_runtime.h>
#include <cuda_fp16.h>
#include <cstdint>
#include <cstddef>

#define N_CTX 4096
#define D_MODEL 2048

// ---------------- scratch (__device__ globals; allocation-free) ----------------
__device__ __half g_Eh [(size_t)N_CTX * D_MODEL], g_El [(size_t)N_CTX * D_MODEL];
__device__ __half g_QKTh[(size_t)D_MODEL * D_MODEL], g_QKTl[(size_t)D_MODEL * D_MODEL];
__device__ __half g_ETh[(size_t)D_MODEL * N_CTX], g_ETl[(size_t)D_MODEL * N_CTX];
__device__ __half g_OVTh[(size_t)D_MODEL * D_MODEL], g_OVTl[(size_t)D_MODEL * D_MODEL];
__device__ __half g_qh [(size_t)N_CTX * D_MODEL], g_ql [(size_t)N_CTX * D_MODEL];
__device__ float  g_scores[(size_t)N_CTX * N_CTX];
__device__ __half g_Ph [(size_t)N_CTX * N_CTX], g_Pl [(size_t)N_CTX * N_CTX];
__device__ __half g_cth[(size_t)N_CTX * D_MODEL], g_ctl[(size_t)N_CTX * D_MODEL];

// ---------------- PTX helpers (baseline ISA only: sm_80/sm_90-safe) ----------------
__device__ __forceinline__ uint32_t s2u(const void* p) {
    uint32_t a;
    asm("{ .reg .u64 t; cvta.to.shared.u64 t, %1; cvt.u32.u64 %0, t; }" : "=r"(a) : "l"(p));
    return a;
}
__device__ __forceinline__ void cp16(uint32_t d, const void* s) {
    asm volatile("cp.async.cg.shared.global [%0], [%1], 16;" :: "r"(d), "l"(s) : "memory");
}
__device__ __forceinline__ void cp_commit() { asm volatile("cp.async.commit_group;" ::: "memory"); }
__device__ __forceinline__ void cp_wait1()  { asm volatile("cp.async.wait_group 1;" ::: "memory"); }
__device__ __forceinline__ void cp_wait0()  { asm volatile("cp.async.wait_group 0;" ::: "memory"); }
__device__ __forceinline__ void ldmx4(uint32_t& r0, uint32_t& r1, uint32_t& r2, uint32_t& r3, uint32_t a) {
    asm volatile("ldmatrix.sync.aligned.m8n8.x4.shared.b16 {%0,%1,%2,%3}, [%4];"
                 : "=r"(r0), "=r"(r1), "=r"(r2), "=r"(r3) : "r"(a));
}
__device__ __forceinline__ void mma16816(float* c, const uint32_t* a, uint32_t b0, uint32_t b1) {
    asm volatile(
        "mma.sync.aligned.m16n8k16.row.col.f32.f16.f16.f32 "
        "{%0,%1,%2,%3}, {%4,%5,%6,%7}, {%8,%9}, {%0,%1,%2,%3};"
        : "+f"(c[0]), "+f"(c[1]), "+f"(c[2]), "+f"(c[3])
        : "r"(a[0]), "r"(a[1]), "r"(a[2]), "r"(a[3]), "r"(b0), "r"(b1));
}

// ---------------- tile loader: 128 rows x 64 halves, XOR-swizzled 128B rows ----------------
__device__ __forceinline__ void ld_tile(uint32_t dst, const __half* __restrict__ src,
                                        int row0, int kbase, int K, int tid)
{
    const int r  = tid >> 1;           // 0..127
    const int cb = (tid & 1) * 4;      // chunk base 0 or 4
    const __half* g = src + (size_t)(row0 + r) * K + kbase;
    const uint32_t rowoff = dst + r * 128;
    const int rx = r & 7;
    #pragma unroll
    for (int c = 0; c < 4; c++) {
        const int ch = cb + c;
        cp16(rowoff + ((ch ^ rx) << 4), g + ch * 8);
    }
}

// ---------------- split-fp16 HMMA GEMM: C[M,N] = A[M,K] @ B[N,K]^T ----------------
// 3 K-segments: Ah*Bh + Ah*Bl + Al*Bh into one fp32 accumulator set.
// MODE: 0 dense, 1 causal tile-skip, 2 k-truncated at diagonal block.
// SPLITOUT: 0 -> fp32 C ; 1 -> (hi,lo) fp16 C.
template<int MODE, int SPLITOUT>
__global__ __launch_bounds__(256) void gemm_hmma(
    const __half* __restrict__ Ah, const __half* __restrict__ Al,
    const __half* __restrict__ Bh, const __half* __restrict__ Bl,
    float* __restrict__ Cf, __half* __restrict__ Ch, __half* __restrict__ Cl,
    int N, int K)
{
    const int rowBase = blockIdx.y * 128;
    const int colBase = blockIdx.x * 128;
    if (MODE == 1 && colBase > rowBase) return;
    const int kEnd = (MODE == 2) ? (rowBase + 128) : K;
    const int NC = kEnd >> 6;          // 64-half chunks per segment
    const int T  = NC * 3;

    extern __shared__ char smraw[];
    const uint32_t sb = (s2u(smraw) + 127) & ~127u;
    const int tid = threadIdx.x;

    const __half* const Asrc[3] = {Ah, Ah, Al};
    const __half* const Bsrc[3] = {Bh, Bl, Bh};

    // software-pipelined load cursor
    int ls = 0, lk = 0;
    ld_tile(sb,         Asrc[0], rowBase, 0, K, tid);
    ld_tile(sb + 16384, Bsrc[0], colBase, 0, K, tid);
    cp_commit();
    if (++lk == NC) { lk = 0; ++ls; }

    const int warp = tid >> 5, lane = tid & 31;
    const int wM = (warp & 3) * 32;    // 4 warp-rows x 32
    const int wN = (warp >> 2) * 64;   // 2 warp-cols x 64

    float acc[2][8][4];
    #pragma unroll
    for (int mt = 0; mt < 2; mt++)
        #pragma unroll
        for (int n = 0; n < 8; n++)
            #pragma unroll
            for (int j = 0; j < 4; j++) acc[mt][n][j] = 0.f;

    // precomputed ldmatrix lane geometry
    const int aRowOff = (lane & 7) + (lane & 8);          // A: row within 16-row tile
    const int aChOff  = (lane >> 4) & 1;                  // A: +chunk
    const int bRowOff = (lane & 7) + ((lane & 16) >> 1);  // B: row within 16-row tile
    const int bChOff  = (lane >> 3) & 1;                  // B: +chunk

    for (int it = 0; it < T; it++) {
        if (it + 1 < T) {
            const uint32_t st = sb + ((it + 1) & 1) * 32768;
            ld_tile(st,         Asrc[ls], rowBase, lk * 64, K, tid);
            ld_tile(st + 16384, Bsrc[ls], colBase, lk * 64, K, tid);
            cp_commit();
            if (++lk == NC) { lk = 0; ++ls; }
            cp_wait1();
        } else {
            cp_wait0();
        }
        __syncthreads();

        const uint32_t stA = sb + (it & 1) * 32768;
        const uint32_t stB = stA + 16384;

        #pragma unroll
        for (int kk = 0; kk < 4; kk++) {
            uint32_t a[2][4];
            #pragma unroll
            for (int mt = 0; mt < 2; mt++) {
                const int r  = wM + mt * 16 + aRowOff;
                const int ch = 2 * kk + aChOff;
                ldmx4(a[mt][0], a[mt][1], a[mt][2], a[mt][3],
                      stA + r * 128 + ((ch ^ (r & 7)) << 4));
            }
            #pragma unroll
            for (int nt = 0; nt < 4; nt++) {
                const int r  = wN + nt * 16 + bRowOff;
                const int ch = 2 * kk + bChOff;
                uint32_t b0, b1, b2, b3;
                ldmx4(b0, b1, b2, b3, stB + r * 128 + ((ch ^ (r & 7)) << 4));
                #pragma unroll
                for (int mt = 0; mt < 2; mt++) {
                    mma16816(acc[mt][nt * 2],     a[mt], b0, b1);
                    mma16816(acc[mt][nt * 2 + 1], a[mt], b2, b3);
                }
            }
        }
        __syncthreads();   // stage consumed; safe for next overwrite
    }

    // ---------------- epilogue ----------------
    const int g  = lane >> 2;
    const int t4 = lane & 3;
    #pragma unroll
    for (int mt = 0; mt < 2; mt++) {
        const int row0 = rowBase + wM + mt * 16 + g;
        #pragma unroll
        for (int n = 0; n < 8; n++) {
            const int col = colBase + wN + n * 8 + t4 * 2;
            if (SPLITOUT == 0) {
                *(float2*)(Cf + (size_t)row0 * N + col) =
                    make_float2(acc[mt][n][0], acc[mt][n][1]);
                *(float2*)(Cf + (size_t)(row0 + 8) * N + col) =
                    make_float2(acc[mt][n][2], acc[mt][n][3]);
            } else {
                #pragma unroll
                for (int hrow = 0; hrow < 2; hrow++) {
                    const float v0 = acc[mt][n][hrow * 2], v1 = acc[mt][n][hrow * 2 + 1];
                    const __half h0 = __float2half(v0), h1 = __float2half(v1);
                    const size_t o = (size_t)(row0 + hrow * 8) * N + col;
                    *(__half2*)(Ch + o) = __halves2half2(h0, h1);
                    *(__half2*)(Cl + o) = __halves2half2(
                        __float2half(v0 - __half2float(h0)),
                        __float2half(v1 - __half2float(h1)));
                }
            }
        }
    }
}

// ---------------- fp32 -> (hi,lo) fp16 split, same layout ----------------
__global__ __launch_bounds__(256) void split_rm(const float* __restrict__ X,
                                                __half* __restrict__ H, __half* __restrict__ L, int n4)
{
    int i = blockIdx.x * 256 + threadIdx.x;
    if (i >= n4) return;
    float4 v = ((const float4*)X)[i];
    float vs[4] = {v.x, v.y, v.z, v.w};
    __half h[4], l[4];
    #pragma unroll
    for (int j = 0; j < 4; j++) {
        h[j] = __float2half(vs[j]);
        l[j] = __float2half(vs[j] - __half2float(h[j]));
    }
    ((__half2*)H)[2 * i]     = __halves2half2(h[0], h[1]);
    ((__half2*)H)[2 * i + 1] = __halves2half2(h[2], h[3]);
    ((__half2*)L)[2 * i]     = __halves2half2(l[0], l[1]);
    ((__half2*)L)[2 * i + 1] = __halves2half2(l[2], l[3]);
}

// ---------------- fp32 [R,C] -> transposed (hi,lo) fp16 [C,R] ----------------
__global__ __launch_bounds__(256) void tsplit(const float* __restrict__ X,
                                              __half* __restrict__ H, __half* __restrict__ L, int R, int C)
{
    __shared__ float tile[32][33];
    const int tx = threadIdx.x, ty = threadIdx.y;   // 32 x 8
    const int c0 = blockIdx.x * 32, r0 = blockIdx.y * 32;
    #pragma unroll
    for (int i = 0; i < 32; i += 8)
        tile[ty + i][tx] = X[(size_t)(r0 + ty + i) * C + c0 + tx];
    __syncthreads();
    #pragma unroll
    for (int i = 0; i < 32; i += 8) {
        float v = tile[tx][ty + i];
        __half h = __float2half(v);
        size_t o = (size_t)(c0 + ty + i) * R + r0 + tx;
        H[o] = h;
        L[o] = __float2half(v - __half2float(h));
    }
}

// ---------------- causal softmax, fused fp16 split output ----------------
__global__ __launch_bounds__(256) void softmax_split(const float* __restrict__ S,
                                                     __half* __restrict__ Ph, __half* __restrict__ Pl)
{
    __shared__ float buf[N_CTX];
    __shared__ float red[256];
    const int i = blockIdx.x, t = threadIdx.x;
    const int n = i + 1;
    const float* row = S + (size_t)i * N_CTX;

    float m = -3.0e38f;
    for (int j = t; j < n; j += 256) { float v = row[j]; buf[j] = v; m = fmaxf(m, v); }
    red[t] = m;
    __syncthreads();
    for (int s2 = 128; s2 > 0; s2 >>= 1) {
        if (t < s2) red[t] = fmaxf(red[t], red[t + s2]);
        __syncthreads();
    }
    m = red[0];
    __syncthreads();

    float s = 0.f;
    for (int j = t; j < n; j += 256) { float e = expf(buf[j] - m); buf[j] = e; s += e; }
    red[t] = s;
    __syncthreads();
    for (int s2 = 128; s2 > 0; s2 >>= 1) {
        if (t < s2) red[t] += red[t + s2];
        __syncthreads();
    }
    const float inv = 1.0f / red[0];

    const int zEnd = ((i >> 7) + 1) << 7;   // zero through the 128-block boundary
    for (int j = t; j < zEnd; j += 256) {
        float p = (j < n) ? buf[j] * inv : 0.0f;
        __half h = __float2half(p);
        const size_t o = (size_t)i * N_CTX + j;
        Ph[o] = h;
        Pl[o] = __float2half(p - __half2float(h));
    }
}

// ---------------------------------------------------------------------------
extern "C" void kernel_launch(void* const* d_in, const int* in_sizes, int n_in,
                              void* d_out, int out_size)
{
    const float* emb = (const float*)d_in[0];   // [4096, 2048]
    const float* qk  = (const float*)d_in[1];   // [2048, 2048]
    const float* ov  = (const float*)d_in[2];   // [2048, 2048]
    float* out = (float*)d_out;                 // [4096, 2048]

    __half *Eh, *El, *QKTh, *QKTl, *ETh, *ETl, *OVTh, *OVTl, *qh, *ql, *Ph, *Pl, *cth, *ctl;
    float* scores;
    cudaGetSymbolAddress((void**)&Eh, g_Eh);     cudaGetSymbolAddress((void**)&El, g_El);
    cudaGetSymbolAddress((void**)&QKTh, g_QKTh); cudaGetSymbolAddress((void**)&QKTl, g_QKTl);
    cudaGetSymbolAddress((void**)&ETh, g_ETh);   cudaGetSymbolAddress((void**)&ETl, g_ETl);
    cudaGetSymbolAddress((void**)&OVTh, g_OVTh); cudaGetSymbolAddress((void**)&OVTl, g_OVTl);
    cudaGetSymbolAddress((void**)&qh, g_qh);     cudaGetSymbolAddress((void**)&ql, g_ql);
    cudaGetSymbolAddress((void**)&Ph, g_Ph);     cudaGetSymbolAddress((void**)&Pl, g_Pl);
    cudaGetSymbolAddress((void**)&cth, g_cth);   cudaGetSymbolAddress((void**)&ctl, g_ctl);
    cudaGetSymbolAddress((void**)&scores, g_scores);

    const int SMEM = 2 * 32768 + 128;
    cudaFuncSetAttribute(gemm_hmma<0,1>, cudaFuncAttributeMaxDynamicSharedMemorySize, SMEM);
    cudaFuncSetAttribute(gemm_hmma<1,0>, cudaFuncAttributeMaxDynamicSharedMemorySize, SMEM);
    cudaFuncSetAttribute(gemm_hmma<2,1>, cudaFuncAttributeMaxDynamicSharedMemorySize, SMEM);
    cudaFuncSetAttribute(gemm_hmma<0,0>, cudaFuncAttributeMaxDynamicSharedMemorySize, SMEM);

    // operand prep
    split_rm<<<(N_CTX * D_MODEL / 4 + 255) / 256, 256>>>(emb, Eh, El, N_CTX * D_MODEL / 4);
    tsplit<<<dim3(D_MODEL / 32, D_MODEL / 32), dim3(32, 8)>>>(qk, QKTh, QKTl, D_MODEL, D_MODEL);
    tsplit<<<dim3(D_MODEL / 32, D_MODEL / 32), dim3(32, 8)>>>(ov, OVTh, OVTl, D_MODEL, D_MODEL);
    tsplit<<<dim3(D_MODEL / 32, N_CTX / 32), dim3(32, 8)>>>(emb, ETh, ETl, N_CTX, D_MODEL);

    // 1) q = E @ QK            (B = QK^T, K-major), split output
    gemm_hmma<0,1><<<dim3(D_MODEL / 128, N_CTX / 128), 256, SMEM>>>(
        Eh, El, QKTh, QKTl, nullptr, qh, ql, D_MODEL, D_MODEL);
    // 2) scores = q @ E^T      causal tile-skip, fp32 output
    gemm_hmma<1,0><<<dim3(N_CTX / 128, N_CTX / 128), 256, SMEM>>>(
        qh, ql, Eh, El, scores, nullptr, nullptr, N_CTX, D_MODEL);
    // 3) softmax + split
    softmax_split<<<N_CTX, 256>>>(scores, Ph, Pl);
    // 4) ctx = P @ E           (B = E^T, K-major over j), k-truncated, split output
    gemm_hmma<2,1><<<dim3(D_MODEL / 128, N_CTX / 128), 256, SMEM>>>(
        Ph, Pl, ETh, ETl, nullptr, cth, ctl, D_MODEL, N_CTX);
    // 5) out = ctx @ OV        (B = OV^T, K-major), fp32 output
    gemm_hmma<0,0><<<dim3(D_MODEL / 128, N_CTX / 128), 256, SMEM>>>(
        cth, ctl, OVTh, OVTl, out, nullptr, nullptr, D_MODEL, D_MODEL);
}

// round 5
// speedup vs baseline: 2.5241x; 1.1574x over previous
#include <cuda_runtime.h>
#include <cuda_fp16.h>
#include <cstdint>
#include <cstddef>

#define N_CTX 4096
#define D_MODEL 2048

// ---------------- scratch (__device__ globals; allocation-free) ----------------
__device__ __half g_Eh [(size_t)N_CTX * D_MODEL], g_El [(size_t)N_CTX * D_MODEL];
__device__ __half g_QKTh[(size_t)D_MODEL * D_MODEL], g_QKTl[(size_t)D_MODEL * D_MODEL];
__device__ __half g_ETh[(size_t)D_MODEL * N_CTX], g_ETl[(size_t)D_MODEL * N_CTX];
__device__ __half g_OVTh[(size_t)D_MODEL * D_MODEL], g_OVTl[(size_t)D_MODEL * D_MODEL];
__device__ __half g_qh [(size_t)N_CTX * D_MODEL], g_ql [(size_t)N_CTX * D_MODEL];
__device__ float  g_scores[(size_t)N_CTX * N_CTX];
__device__ __half g_Ph [(size_t)N_CTX * N_CTX], g_Pl [(size_t)N_CTX * N_CTX];
__device__ __half g_cth[(size_t)N_CTX * D_MODEL], g_ctl[(size_t)N_CTX * D_MODEL];

// ---------------- PTX helpers (baseline ISA; no tcgen05) ----------------
__device__ __forceinline__ uint32_t s2u(const void* p) {
    uint32_t a;
    asm("{ .reg .u64 t; cvta.to.shared.u64 t, %1; cvt.u32.u64 %0, t; }" : "=r"(a) : "l"(p));
    return a;
}
__device__ __forceinline__ void cp16(uint32_t d, const void* s) {
    asm volatile("cp.async.cg.shared.global [%0], [%1], 16;" :: "r"(d), "l"(s) : "memory");
}
__device__ __forceinline__ void cp_commit() { asm volatile("cp.async.commit_group;" ::: "memory"); }
__device__ __forceinline__ void cp_wait1()  { asm volatile("cp.async.wait_group 1;" ::: "memory"); }
__device__ __forceinline__ void cp_wait0()  { asm volatile("cp.async.wait_group 0;" ::: "memory"); }
__device__ __forceinline__ void ldmx4(uint32_t& r0, uint32_t& r1, uint32_t& r2, uint32_t& r3, uint32_t a) {
    asm volatile("ldmatrix.sync.aligned.m8n8.x4.shared.b16 {%0,%1,%2,%3}, [%4];"
                 : "=r"(r0), "=r"(r1), "=r"(r2), "=r"(r3) : "r"(a));
}
__device__ __forceinline__ void mma16816(float* c, const uint32_t* a, uint32_t b0, uint32_t b1) {
    asm volatile(
        "mma.sync.aligned.m16n8k16.row.col.f32.f16.f16.f32 "
        "{%0,%1,%2,%3}, {%4,%5,%6,%7}, {%8,%9}, {%0,%1,%2,%3};"
        : "+f"(c[0]), "+f"(c[1]), "+f"(c[2]), "+f"(c[3])
        : "r"(a[0]), "r"(a[1]), "r"(a[2]), "r"(a[3]), "r"(b0), "r"(b1));
}

// ---------------- tile loader: 128 rows x 64 halves, XOR-swizzled 128B rows ----------------
__device__ __forceinline__ void ld_tile(uint32_t dst, const __half* __restrict__ src,
                                        int row0, int kbase, int K, int tid)
{
    const int r  = tid >> 1;           // 0..127
    const int cb = (tid & 1) * 4;      // chunk base 0 or 4
    const __half* g = src + (size_t)(row0 + r) * K + kbase;
    const uint32_t rowoff = dst + r * 128;
    const int rx = r & 7;
    #pragma unroll
    for (int c = 0; c < 4; c++) {
        const int ch = cb + c;
        cp16(rowoff + ((ch ^ rx) << 4), g + ch * 8);
    }
}

// load one pipeline stage: Ah, Al, Bh, Bl tiles (4 x 16 KB)
__device__ __forceinline__ void ld_stage(uint32_t st,
    const __half* Ah, const __half* Al, const __half* Bh, const __half* Bl,
    int rowBase, int colBase, int kbase, int K, int tid)
{
    ld_tile(st,         Ah, rowBase, kbase, K, tid);
    ld_tile(st + 16384, Al, rowBase, kbase, K, tid);
    ld_tile(st + 32768, Bh, colBase, kbase, K, tid);
    ld_tile(st + 49152, Bl, colBase, kbase, K, tid);
    cp_commit();
}

// ---------------- split-fp16 HMMA GEMM: C[M,N] = A[M,K] @ B[N,K]^T ----------------
// Per K-chunk: all 3 split terms (AhBh + AhBl + AlBh) from one resident stage.
// MODE: 0 dense, 1 causal tile-skip, 2 k-truncated. SPLITOUT: 0 fp32 / 1 split fp16.
template<int MODE, int SPLITOUT>
__global__ __launch_bounds__(256) void gemm_hmma(
    const __half* __restrict__ Ah, const __half* __restrict__ Al,
    const __half* __restrict__ Bh, const __half* __restrict__ Bl,
    float* __restrict__ Cf, __half* __restrict__ Ch, __half* __restrict__ Cl,
    int N, int K)
{
    const int rowBase = blockIdx.y * 128;
    const int colBase = blockIdx.x * 128;
    if (MODE == 1 && colBase > rowBase) return;
    const int kEnd = (MODE == 2) ? (rowBase + 128) : K;
    const int T = kEnd >> 6;           // 64-half chunks (always >= 2 here)

    extern __shared__ char smraw[];
    const uint32_t sb = (s2u(smraw) + 127) & ~127u;
    const int tid = threadIdx.x;

    // prologue: stages 0 and 1
    ld_stage(sb,         Ah, Al, Bh, Bl, rowBase, colBase, 0,  K, tid);
    ld_stage(sb + 65536, Ah, Al, Bh, Bl, rowBase, colBase, 64, K, tid);

    const int warp = tid >> 5, lane = tid & 31;
    const int wM = (warp & 3) * 32;    // 4 warp-rows x 32
    const int wN = (warp >> 2) * 64;   // 2 warp-cols x 64

    float acc[2][8][4];
    #pragma unroll
    for (int mt = 0; mt < 2; mt++)
        #pragma unroll
        for (int n = 0; n < 8; n++)
            #pragma unroll
            for (int j = 0; j < 4; j++) acc[mt][n][j] = 0.f;

    const int aRowOff = (lane & 7) + (lane & 8);
    const int aChOff  = (lane >> 4) & 1;
    const int bRowOff = (lane & 7) + ((lane & 16) >> 1);
    const int bChOff  = (lane >> 3) & 1;

    uint32_t stageOff[3] = {0u, 65536u, 131072u};

    for (int it = 0; it < T; it++) {
        if (it < T - 1) cp_wait1(); else cp_wait0();
        __syncthreads();
        if (it + 2 < T)
            ld_stage(sb + stageOff[(it + 2) % 3], Ah, Al, Bh, Bl,
                     rowBase, colBase, (it + 2) << 6, K, tid);

        const uint32_t stA = sb + stageOff[it % 3];
        const uint32_t stB = stA + 32768;

        #pragma unroll
        for (int kk = 0; kk < 4; kk++) {
            uint32_t aH[2][4], aL[2][4];
            #pragma unroll
            for (int mt = 0; mt < 2; mt++) {
                const int r  = wM + mt * 16 + aRowOff;
                const int ch = 2 * kk + aChOff;
                const uint32_t off = r * 128 + ((ch ^ (r & 7)) << 4);
                ldmx4(aH[mt][0], aH[mt][1], aH[mt][2], aH[mt][3], stA + off);
                ldmx4(aL[mt][0], aL[mt][1], aL[mt][2], aL[mt][3], stA + 16384 + off);
            }
            #pragma unroll
            for (int nt = 0; nt < 4; nt++) {
                const int r  = wN + nt * 16 + bRowOff;
                const int ch = 2 * kk + bChOff;
                const uint32_t off = r * 128 + ((ch ^ (r & 7)) << 4);
                uint32_t h0, h1, h2, h3, l0, l1, l2, l3;
                ldmx4(h0, h1, h2, h3, stB + off);
                ldmx4(l0, l1, l2, l3, stB + 16384 + off);
                #pragma unroll
                for (int mt = 0; mt < 2; mt++) {
                    mma16816(acc[mt][nt * 2],     aH[mt], h0, h1);
                    mma16816(acc[mt][nt * 2 + 1], aH[mt], h2, h3);
                    mma16816(acc[mt][nt * 2],     aH[mt], l0, l1);
                    mma16816(acc[mt][nt * 2 + 1], aH[mt], l2, l3);
                    mma16816(acc[mt][nt * 2],     aL[mt], h0, h1);
                    mma16816(acc[mt][nt * 2 + 1], aL[mt], h2, h3);
                }
            }
        }
    }

    // ---------------- epilogue ----------------
    const int g  = lane >> 2;
    const int t4 = lane & 3;
    #pragma unroll
    for (int mt = 0; mt < 2; mt++) {
        const int row0 = rowBase + wM + mt * 16 + g;
        #pragma unroll
        for (int n = 0; n < 8; n++) {
            const int col = colBase + wN + n * 8 + t4 * 2;
            if (SPLITOUT == 0) {
                *(float2*)(Cf + (size_t)row0 * N + col) =
                    make_float2(acc[mt][n][0], acc[mt][n][1]);
                *(float2*)(Cf + (size_t)(row0 + 8) * N + col) =
                    make_float2(acc[mt][n][2], acc[mt][n][3]);
            } else {
                #pragma unroll
                for (int hrow = 0; hrow < 2; hrow++) {
                    const float v0 = acc[mt][n][hrow * 2], v1 = acc[mt][n][hrow * 2 + 1];
                    const __half h0 = __float2half(v0), h1 = __float2half(v1);
                    const size_t o = (size_t)(row0 + hrow * 8) * N + col;
                    *(__half2*)(Ch + o) = __halves2half2(h0, h1);
                    *(__half2*)(Cl + o) = __halves2half2(
                        __float2half(v0 - __half2float(h0)),
                        __float2half(v1 - __half2float(h1)));
                }
            }
        }
    }
}

// ---------------- fp32 -> (hi,lo) fp16 split, same layout ----------------
__global__ __launch_bounds__(256) void split_rm(const float* __restrict__ X,
                                                __half* __restrict__ H, __half* __restrict__ L, int n4)
{
    int i = blockIdx.x * 256 + threadIdx.x;
    if (i >= n4) return;
    float4 v = ((const float4*)X)[i];
    float vs[4] = {v.x, v.y, v.z, v.w};
    __half h[4], l[4];
    #pragma unroll
    for (int j = 0; j < 4; j++) {
        h[j] = __float2half(vs[j]);
        l[j] = __float2half(vs[j] - __half2float(h[j]));
    }
    ((__half2*)H)[2 * i]     = __halves2half2(h[0], h[1]);
    ((__half2*)H)[2 * i + 1] = __halves2half2(h[2], h[3]);
    ((__half2*)L)[2 * i]     = __halves2half2(l[0], l[1]);
    ((__half2*)L)[2 * i + 1] = __halves2half2(l[2], l[3]);
}

// ---------------- fp32 [R,C] -> transposed (hi,lo) fp16 [C,R] ----------------
__global__ __launch_bounds__(256) void tsplit(const float* __restrict__ X,
                                              __half* __restrict__ H, __half* __restrict__ L, int R, int C)
{
    __shared__ float tile[32][33];
    const int tx = threadIdx.x, ty = threadIdx.y;   // 32 x 8
    const int c0 = blockIdx.x * 32, r0 = blockIdx.y * 32;
    #pragma unroll
    for (int i = 0; i < 32; i += 8)
        tile[ty + i][tx] = X[(size_t)(r0 + ty + i) * C + c0 + tx];
    __syncthreads();
    #pragma unroll
    for (int i = 0; i < 32; i += 8) {
        float v = tile[tx][ty + i];
        __half h = __float2half(v);
        size_t o = (size_t)(c0 + ty + i) * R + r0 + tx;
        H[o] = h;
        L[o] = __float2half(v - __half2float(h));
    }
}

// ---------------- causal softmax, fused fp16 split output ----------------
__global__ __launch_bounds__(256) void softmax_split(const float* __restrict__ S,
                                                     __half* __restrict__ Ph, __half* __restrict__ Pl)
{
    __shared__ float buf[N_CTX];
    __shared__ float red[256];
    const int i = blockIdx.x, t = threadIdx.x;
    const int n = i + 1;
    const float* row = S + (size_t)i * N_CTX;

    float m = -3.0e38f;
    for (int j = t; j < n; j += 256) { float v = row[j]; buf[j] = v; m = fmaxf(m, v); }
    red[t] = m;
    __syncthreads();
    for (int s2 = 128; s2 > 0; s2 >>= 1) {
        if (t < s2) red[t] = fmaxf(red[t], red[t + s2]);
        __syncthreads();
    }
    m = red[0];
    __syncthreads();

    float s = 0.f;
    for (int j = t; j < n; j += 256) { float e = expf(buf[j] - m); buf[j] = e; s += e; }
    red[t] = s;
    __syncthreads();
    for (int s2 = 128; s2 > 0; s2 >>= 1) {
        if (t < s2) red[t] += red[t + s2];
        __syncthreads();
    }
    const float inv = 1.0f / red[0];

    const int zEnd = ((i >> 7) + 1) << 7;   // zero through the 128-block boundary
    for (int j = t; j < zEnd; j += 256) {
        float p = (j < n) ? buf[j] * inv : 0.0f;
        __half h = __float2half(p);
        const size_t o = (size_t)i * N_CTX + j;
        Ph[o] = h;
        Pl[o] = __float2half(p - __half2float(h));
    }
}

// ---------------------------------------------------------------------------
extern "C" void kernel_launch(void* const* d_in, const int* in_sizes, int n_in,
                              void* d_out, int out_size)
{
    const float* emb = (const float*)d_in[0];   // [4096, 2048]
    const float* qk  = (const float*)d_in[1];   // [2048, 2048]
    const float* ov  = (const float*)d_in[2];   // [2048, 2048]
    float* out = (float*)d_out;                 // [4096, 2048]

    __half *Eh, *El, *QKTh, *QKTl, *ETh, *ETl, *OVTh, *OVTl, *qh, *ql, *Ph, *Pl, *cth, *ctl;
    float* scores;
    cudaGetSymbolAddress((void**)&Eh, g_Eh);     cudaGetSymbolAddress((void**)&El, g_El);
    cudaGetSymbolAddress((void**)&QKTh, g_QKTh); cudaGetSymbolAddress((void**)&QKTl, g_QKTl);
    cudaGetSymbolAddress((void**)&ETh, g_ETh);   cudaGetSymbolAddress((void**)&ETl, g_ETl);
    cudaGetSymbolAddress((void**)&OVTh, g_OVTh); cudaGetSymbolAddress((void**)&OVTl, g_OVTl);
    cudaGetSymbolAddress((void**)&qh, g_qh);     cudaGetSymbolAddress((void**)&ql, g_ql);
    cudaGetSymbolAddress((void**)&Ph, g_Ph);     cudaGetSymbolAddress((void**)&Pl, g_Pl);
    cudaGetSymbolAddress((void**)&cth, g_cth);   cudaGetSymbolAddress((void**)&ctl, g_ctl);
    cudaGetSymbolAddress((void**)&scores, g_scores);

    const int SMEM = 3 * 65536 + 128;
    cudaFuncSetAttribute(gemm_hmma<0,1>, cudaFuncAttributeMaxDynamicSharedMemorySize, SMEM);
    cudaFuncSetAttribute(gemm_hmma<1,0>, cudaFuncAttributeMaxDynamicSharedMemorySize, SMEM);
    cudaFuncSetAttribute(gemm_hmma<2,1>, cudaFuncAttributeMaxDynamicSharedMemorySize, SMEM);
    cudaFuncSetAttribute(gemm_hmma<0,0>, cudaFuncAttributeMaxDynamicSharedMemorySize, SMEM);

    // operand prep
    split_rm<<<(N_CTX * D_MODEL / 4 + 255) / 256, 256>>>(emb, Eh, El, N_CTX * D_MODEL / 4);
    tsplit<<<dim3(D_MODEL / 32, D_MODEL / 32), dim3(32, 8)>>>(qk, QKTh, QKTl, D_MODEL, D_MODEL);
    tsplit<<<dim3(D_MODEL / 32, D_MODEL / 32), dim3(32, 8)>>>(ov, OVTh, OVTl, D_MODEL, D_MODEL);
    tsplit<<<dim3(D_MODEL / 32, N_CTX / 32), dim3(32, 8)>>>(emb, ETh, ETl, N_CTX, D_MODEL);

    // 1) q = E @ QK            (B = QK^T, K-major), split output
    gemm_hmma<0,1><<<dim3(D_MODEL / 128, N_CTX / 128), 256, SMEM>>>(
        Eh, El, QKTh, QKTl, nullptr, qh, ql, D_MODEL, D_MODEL);
    // 2) scores = q @ E^T      causal tile-skip, fp32 output
    gemm_hmma<1,0><<<dim3(N_CTX / 128, N_CTX / 128), 256, SMEM>>>(
        qh, ql, Eh, El, scores, nullptr, nullptr, N_CTX, D_MODEL);
    // 3) softmax + split
    softmax_split<<<N_CTX, 256>>>(scores, Ph, Pl);
    // 4) ctx = P @ E           (B = E^T, K-major over j), k-truncated, split output
    gemm_hmma<2,1><<<dim3(D_MODEL / 128, N_CTX / 128), 256, SMEM>>>(
        Ph, Pl, ETh, ETl, nullptr, cth, ctl, D_MODEL, N_CTX);
    // 5) out = ctx @ OV        (B = OV^T, K-major), fp32 output
    gemm_hmma<0,0><<<dim3(D_MODEL / 128, N_CTX / 128), 256, SMEM>>>(
        cth, ctl, OVTh, OVTl, out, nullptr, nullptr, D_MODEL, D_MODEL);
}

// round 6
// speedup vs baseline: 2.9665x; 1.1753x over previous
#include <cuda_runtime.h>
#include <cuda_fp16.h>
#include <cstdint>
#include <cstddef>

#define N_CTX 4096
#define D_MODEL 2048

// ---------------- scratch (__device__ globals; allocation-free) ----------------
__device__ __half g_Eh [(size_t)N_CTX * D_MODEL], g_El [(size_t)N_CTX * D_MODEL];
__device__ __half g_QKTh[(size_t)D_MODEL * D_MODEL], g_QKTl[(size_t)D_MODEL * D_MODEL];
__device__ __half g_ETh[(size_t)D_MODEL * N_CTX], g_ETl[(size_t)D_MODEL * N_CTX];
__device__ __half g_OVTh[(size_t)D_MODEL * D_MODEL], g_OVTl[(size_t)D_MODEL * D_MODEL];
__device__ __half g_qh [(size_t)N_CTX * D_MODEL], g_ql [(size_t)N_CTX * D_MODEL];
__device__ float  g_qf [(size_t)N_CTX * D_MODEL];
__device__ float  g_scores[(size_t)N_CTX * N_CTX];
__device__ __half g_Ph [(size_t)N_CTX * N_CTX], g_Pl [(size_t)N_CTX * N_CTX];
__device__ __half g_cth[(size_t)N_CTX * D_MODEL], g_ctl[(size_t)N_CTX * D_MODEL];

// ---------------- PTX helpers (baseline ISA; no tcgen05) ----------------
__device__ __forceinline__ uint32_t s2u(const void* p) {
    uint32_t a;
    asm("{ .reg .u64 t; cvta.to.shared.u64 t, %1; cvt.u32.u64 %0, t; }" : "=r"(a) : "l"(p));
    return a;
}
__device__ __forceinline__ void cp16(uint32_t d, const void* s) {
    asm volatile("cp.async.cg.shared.global [%0], [%1], 16;" :: "r"(d), "l"(s) : "memory");
}
__device__ __forceinline__ void cp_commit() { asm volatile("cp.async.commit_group;" ::: "memory"); }
__device__ __forceinline__ void cp_wait1()  { asm volatile("cp.async.wait_group 1;" ::: "memory"); }
__device__ __forceinline__ void cp_wait0()  { asm volatile("cp.async.wait_group 0;" ::: "memory"); }
__device__ __forceinline__ void ldmx4(uint32_t& r0, uint32_t& r1, uint32_t& r2, uint32_t& r3, uint32_t a) {
    asm volatile("ldmatrix.sync.aligned.m8n8.x4.shared.b16 {%0,%1,%2,%3}, [%4];"
                 : "=r"(r0), "=r"(r1), "=r"(r2), "=r"(r3) : "r"(a));
}
__device__ __forceinline__ void mma16816(float* c, const uint32_t* a, uint32_t b0, uint32_t b1) {
    asm volatile(
        "mma.sync.aligned.m16n8k16.row.col.f32.f16.f16.f32 "
        "{%0,%1,%2,%3}, {%4,%5,%6,%7}, {%8,%9}, {%0,%1,%2,%3};"
        : "+f"(c[0]), "+f"(c[1]), "+f"(c[2]), "+f"(c[3])
        : "r"(a[0]), "r"(a[1]), "r"(a[2]), "r"(a[3]), "r"(b0), "r"(b1));
}

// ---------------- tile loader: 128 rows x 64 halves, XOR-swizzled 128B rows ----------------
__device__ __forceinline__ void ld_tile(uint32_t dst, const __half* __restrict__ src,
                                        int row0, int kbase, int K, int tid)
{
    const int r  = tid >> 1;
    const int cb = (tid & 1) * 4;
    const __half* g = src + (size_t)(row0 + r) * K + kbase;
    const uint32_t rowoff = dst + r * 128;
    const int rx = r & 7;
    #pragma unroll
    for (int c = 0; c < 4; c++) {
        const int ch = cb + c;
        cp16(rowoff + ((ch ^ rx) << 4), g + ch * 8);
    }
}

template<int TERMS>
__device__ __forceinline__ void ld_stage(uint32_t st,
    const __half* Ah, const __half* Al, const __half* Bh, const __half* Bl,
    int rowBase, int colBase, int kbase, int K, int tid)
{
    constexpr uint32_t AB = (TERMS == 3) ? 32768u : 16384u;
    ld_tile(st, Ah, rowBase, kbase, K, tid);
    if (TERMS == 3) ld_tile(st + 16384, Al, rowBase, kbase, K, tid);
    ld_tile(st + AB, Bh, colBase, kbase, K, tid);
    if (TERMS == 3) ld_tile(st + AB + 16384, Bl, colBase, kbase, K, tid);
    cp_commit();
}

// ---------------- split-fp16 HMMA GEMM: C[M,N] = A[M,K] @ B[N,K]^T ----------------
// TERMS==3: AhBh + AhBl + AlBh. TERMS==1: AhBh only.
// MODE: 0 dense, 1 causal tile-skip, 2 k-truncated.
// SPLITOUT: 0 fp32 C ; 1 split fp16 C ; 2 both.
template<int MODE, int SPLITOUT, int TERMS>
__global__ __launch_bounds__(256) void gemm_hmma(
    const __half* __restrict__ Ah, const __half* __restrict__ Al,
    const __half* __restrict__ Bh, const __half* __restrict__ Bl,
    float* __restrict__ Cf, __half* __restrict__ Ch, __half* __restrict__ Cl,
    int N, int K)
{
    constexpr uint32_t AB = (TERMS == 3) ? 32768u : 16384u;
    constexpr uint32_t SB = (TERMS == 3) ? 65536u : 32768u;

    const int rowBase = blockIdx.y * 128;
    const int colBase = blockIdx.x * 128;
    if (MODE == 1 && colBase > rowBase) return;
    const int kEnd = (MODE == 2) ? (rowBase + 128) : K;
    const int T = kEnd >> 6;

    extern __shared__ char smraw[];
    const uint32_t sb = (s2u(smraw) + 127) & ~127u;
    const int tid = threadIdx.x;

    ld_stage<TERMS>(sb,      Ah, Al, Bh, Bl, rowBase, colBase, 0,  K, tid);
    ld_stage<TERMS>(sb + SB, Ah, Al, Bh, Bl, rowBase, colBase, 64, K, tid);

    const int warp = tid >> 5, lane = tid & 31;
    const int wM = (warp & 3) * 32;
    const int wN = (warp >> 2) * 64;

    float acc[2][8][4];
    #pragma unroll
    for (int mt = 0; mt < 2; mt++)
        #pragma unroll
        for (int n = 0; n < 8; n++)
            #pragma unroll
            for (int j = 0; j < 4; j++) acc[mt][n][j] = 0.f;

    const int aRowOff = (lane & 7) + (lane & 8);
    const int aChOff  = (lane >> 4) & 1;
    const int bRowOff = (lane & 7) + ((lane & 16) >> 1);
    const int bChOff  = (lane >> 3) & 1;

    for (int it = 0; it < T; it++) {
        if (it < T - 1) cp_wait1(); else cp_wait0();
        __syncthreads();
        if (it + 2 < T)
            ld_stage<TERMS>(sb + ((it + 2) % 3) * SB, Ah, Al, Bh, Bl,
                            rowBase, colBase, (it + 2) << 6, K, tid);

        const uint32_t stA = sb + (it % 3) * SB;
        const uint32_t stB = stA + AB;

        #pragma unroll
        for (int kk = 0; kk < 4; kk++) {
            uint32_t aH[2][4], aL[2][4];
            #pragma unroll
            for (int mt = 0; mt < 2; mt++) {
                const int r  = wM + mt * 16 + aRowOff;
                const int ch = 2 * kk + aChOff;
                const uint32_t off = r * 128 + ((ch ^ (r & 7)) << 4);
                ldmx4(aH[mt][0], aH[mt][1], aH[mt][2], aH[mt][3], stA + off);
                if (TERMS == 3)
                    ldmx4(aL[mt][0], aL[mt][1], aL[mt][2], aL[mt][3], stA + 16384 + off);
            }
            #pragma unroll
            for (int nt = 0; nt < 4; nt++) {
                const int r  = wN + nt * 16 + bRowOff;
                const int ch = 2 * kk + bChOff;
                const uint32_t off = r * 128 + ((ch ^ (r & 7)) << 4);
                uint32_t h0, h1, h2, h3;
                ldmx4(h0, h1, h2, h3, stB + off);
                if (TERMS == 3) {
                    uint32_t l0, l1, l2, l3;
                    ldmx4(l0, l1, l2, l3, stB + 16384 + off);
                    #pragma unroll
                    for (int mt = 0; mt < 2; mt++) {
                        mma16816(acc[mt][nt * 2],     aH[mt], h0, h1);
                        mma16816(acc[mt][nt * 2 + 1], aH[mt], h2, h3);
                        mma16816(acc[mt][nt * 2],     aH[mt], l0, l1);
                        mma16816(acc[mt][nt * 2 + 1], aH[mt], l2, l3);
                        mma16816(acc[mt][nt * 2],     aL[mt], h0, h1);
                        mma16816(acc[mt][nt * 2 + 1], aL[mt], h2, h3);
                    }
                } else {
                    #pragma unroll
                    for (int mt = 0; mt < 2; mt++) {
                        mma16816(acc[mt][nt * 2],     aH[mt], h0, h1);
                        mma16816(acc[mt][nt * 2 + 1], aH[mt], h2, h3);
                    }
                }
            }
        }
    }

    // ---------------- epilogue ----------------
    const int g  = lane >> 2;
    const int t4 = lane & 3;
    #pragma unroll
    for (int mt = 0; mt < 2; mt++) {
        const int row0 = rowBase + wM + mt * 16 + g;
        #pragma unroll
        for (int n = 0; n < 8; n++) {
            const int col = colBase + wN + n * 8 + t4 * 2;
            if (SPLITOUT == 0 || SPLITOUT == 2) {
                *(float2*)(Cf + (size_t)row0 * N + col) =
                    make_float2(acc[mt][n][0], acc[mt][n][1]);
                *(float2*)(Cf + (size_t)(row0 + 8) * N + col) =
                    make_float2(acc[mt][n][2], acc[mt][n][3]);
            }
            if (SPLITOUT >= 1) {
                #pragma unroll
                for (int hrow = 0; hrow < 2; hrow++) {
                    const float v0 = acc[mt][n][hrow * 2], v1 = acc[mt][n][hrow * 2 + 1];
                    const __half h0 = __float2half(v0), h1 = __float2half(v1);
                    const size_t o = (size_t)(row0 + hrow * 8) * N + col;
                    *(__half2*)(Ch + o) = __halves2half2(h0, h1);
                    *(__half2*)(Cl + o) = __halves2half2(
                        __float2half(v0 - __half2float(h0)),
                        __float2half(v1 - __half2float(h1)));
                }
            }
        }
    }
}

// ---------------- fp32 -> (hi,lo) fp16 split ----------------
__global__ __launch_bounds__(256) void split_rm(const float* __restrict__ X,
                                                __half* __restrict__ H, __half* __restrict__ L, int n4)
{
    int i = blockIdx.x * 256 + threadIdx.x;
    if (i >= n4) return;
    float4 v = ((const float4*)X)[i];
    float vs[4] = {v.x, v.y, v.z, v.w};
    __half h[4], l[4];
    #pragma unroll
    for (int j = 0; j < 4; j++) {
        h[j] = __float2half(vs[j]);
        l[j] = __float2half(vs[j] - __half2float(h[j]));
    }
    ((__half2*)H)[2 * i]     = __halves2half2(h[0], h[1]);
    ((__half2*)H)[2 * i + 1] = __halves2half2(h[2], h[3]);
    ((__half2*)L)[2 * i]     = __halves2half2(l[0], l[1]);
    ((__half2*)L)[2 * i + 1] = __halves2half2(l[2], l[3]);
}

// ---------------- fp32 [R,C] -> transposed (hi,lo) fp16 [C,R] ----------------
__global__ __launch_bounds__(256) void tsplit(const float* __restrict__ X,
                                              __half* __restrict__ H, __half* __restrict__ L, int R, int C)
{
    __shared__ float tile[32][33];
    const int tx = threadIdx.x, ty = threadIdx.y;
    const int c0 = blockIdx.x * 32, r0 = blockIdx.y * 32;
    #pragma unroll
    for (int i = 0; i < 32; i += 8)
        tile[ty + i][tx] = X[(size_t)(r0 + ty + i) * C + c0 + tx];
    __syncthreads();
    #pragma unroll
    for (int i = 0; i < 32; i += 8) {
        float v = tile[tx][ty + i];
        __half h = __float2half(v);
        size_t o = (size_t)(c0 + ty + i) * R + r0 + tx;
        H[o] = h;
        L[o] = __float2half(v - __half2float(h));
    }
}

// ---------------- causal softmax with exact recompute of near-max entries ----------------
// Scores come from a cheap 1-term fp16 GEMM (abs err <~2). Any entry within
// MARGIN of the row max is recomputed exactly as fp32 dot(q_i, e_j); tail
// entries keep approx values (true weight < e^-16 -> negligible).
#define RC_MARGIN 20.0f
#define RC_CAP 1024
__global__ __launch_bounds__(256) void softmax_rc(const float* __restrict__ S,
                                                  const float* __restrict__ qf,
                                                  const float* __restrict__ emb,
                                                  __half* __restrict__ Ph, __half* __restrict__ Pl)
{
    __shared__ float buf[N_CTX];
    __shared__ float red[256];
    __shared__ int   list[RC_CAP];
    __shared__ int   cnt;
    const int i = blockIdx.x, t = threadIdx.x;
    const int n = i + 1;
    const float* row = S + (size_t)i * N_CTX;

    // pass 1: load + approx max
    float m = -3.0e38f;
    for (int j = t; j < n; j += 256) { float v = row[j]; buf[j] = v; m = fmaxf(m, v); }
    red[t] = m;
    if (t == 0) cnt = 0;
    __syncthreads();
    for (int s2 = 128; s2 > 0; s2 >>= 1) {
        if (t < s2) red[t] = fmaxf(red[t], red[t + s2]);
        __syncthreads();
    }
    m = red[0];
    __syncthreads();

    // collect candidates near max
    for (int j = t; j < n; j += 256)
        if (buf[j] > m - RC_MARGIN) {
            int p = atomicAdd(&cnt, 1);
            if (p < RC_CAP) list[p] = j;
        }
    __syncthreads();
    const int nc = min(cnt, RC_CAP);

    // exact fp32 recompute, one warp per candidate
    const int warp = t >> 5, lane = t & 31;
    const float4* qp = (const float4*)(qf + (size_t)i * D_MODEL);
    for (int c = warp; c < nc; c += 8) {
        const int j = list[c];
        const float4* ep = (const float4*)(emb + (size_t)j * D_MODEL);
        float s = 0.f;
        #pragma unroll 4
        for (int k = lane; k < D_MODEL / 4; k += 32) {
            float4 a = qp[k], b = ep[k];
            s += a.x * b.x + a.y * b.y + a.z * b.z + a.w * b.w;
        }
        #pragma unroll
        for (int off = 16; off > 0; off >>= 1) s += __shfl_xor_sync(0xFFFFFFFFu, s, off);
        if (lane == 0) buf[j] = s;
    }
    __syncthreads();

    // pass 2: exact max over corrected row
    m = -3.0e38f;
    for (int j = t; j < n; j += 256) m = fmaxf(m, buf[j]);
    red[t] = m;
    __syncthreads();
    for (int s2 = 128; s2 > 0; s2 >>= 1) {
        if (t < s2) red[t] = fmaxf(red[t], red[t + s2]);
        __syncthreads();
    }
    m = red[0];
    __syncthreads();

    // exp + sum
    float s = 0.f;
    for (int j = t; j < n; j += 256) { float e = expf(buf[j] - m); buf[j] = e; s += e; }
    red[t] = s;
    __syncthreads();
    for (int s2 = 128; s2 > 0; s2 >>= 1) {
        if (t < s2) red[t] += red[t + s2];
        __syncthreads();
    }
    const float inv = 1.0f / red[0];

    const int zEnd = ((i >> 7) + 1) << 7;
    for (int j = t; j < zEnd; j += 256) {
        float p = (j < n) ? buf[j] * inv : 0.0f;
        __half h = __float2half(p);
        const size_t o = (size_t)i * N_CTX + j;
        Ph[o] = h;
        Pl[o] = __float2half(p - __half2float(h));
    }
}

// ---------------------------------------------------------------------------
extern "C" void kernel_launch(void* const* d_in, const int* in_sizes, int n_in,
                              void* d_out, int out_size)
{
    const float* emb = (const float*)d_in[0];   // [4096, 2048]
    const float* qk  = (const float*)d_in[1];   // [2048, 2048]
    const float* ov  = (const float*)d_in[2];   // [2048, 2048]
    float* out = (float*)d_out;                 // [4096, 2048]

    __half *Eh, *El, *QKTh, *QKTl, *ETh, *ETl, *OVTh, *OVTl, *qh, *ql, *Ph, *Pl, *cth, *ctl;
    float *scores, *qf;
    cudaGetSymbolAddress((void**)&Eh, g_Eh);     cudaGetSymbolAddress((void**)&El, g_El);
    cudaGetSymbolAddress((void**)&QKTh, g_QKTh); cudaGetSymbolAddress((void**)&QKTl, g_QKTl);
    cudaGetSymbolAddress((void**)&ETh, g_ETh);   cudaGetSymbolAddress((void**)&ETl, g_ETl);
    cudaGetSymbolAddress((void**)&OVTh, g_OVTh); cudaGetSymbolAddress((void**)&OVTl, g_OVTl);
    cudaGetSymbolAddress((void**)&qh, g_qh);     cudaGetSymbolAddress((void**)&ql, g_ql);
    cudaGetSymbolAddress((void**)&Ph, g_Ph);     cudaGetSymbolAddress((void**)&Pl, g_Pl);
    cudaGetSymbolAddress((void**)&cth, g_cth);   cudaGetSymbolAddress((void**)&ctl, g_ctl);
    cudaGetSymbolAddress((void**)&scores, g_scores);
    cudaGetSymbolAddress((void**)&qf, g_qf);

    const int SMEM3 = 3 * 65536 + 128;
    const int SMEM1 = 3 * 32768 + 128;
    cudaFuncSetAttribute(gemm_hmma<0,2,3>, cudaFuncAttributeMaxDynamicSharedMemorySize, SMEM3);
    cudaFuncSetAttribute(gemm_hmma<1,0,1>, cudaFuncAttributeMaxDynamicSharedMemorySize, SMEM1);
    cudaFuncSetAttribute(gemm_hmma<2,1,3>, cudaFuncAttributeMaxDynamicSharedMemorySize, SMEM3);
    cudaFuncSetAttribute(gemm_hmma<0,0,3>, cudaFuncAttributeMaxDynamicSharedMemorySize, SMEM3);

    // operand prep
    split_rm<<<(N_CTX * D_MODEL / 4 + 255) / 256, 256>>>(emb, Eh, El, N_CTX * D_MODEL / 4);
    tsplit<<<dim3(D_MODEL / 32, D_MODEL / 32), dim3(32, 8)>>>(qk, QKTh, QKTl, D_MODEL, D_MODEL);
    tsplit<<<dim3(D_MODEL / 32, D_MODEL / 32), dim3(32, 8)>>>(ov, OVTh, OVTl, D_MODEL, D_MODEL);
    tsplit<<<dim3(D_MODEL / 32, N_CTX / 32), dim3(32, 8)>>>(emb, ETh, ETl, N_CTX, D_MODEL);

    // 1) q = E @ QK : 3-term, split fp16 + fp32 out
    gemm_hmma<0,2,3><<<dim3(D_MODEL / 128, N_CTX / 128), 256, SMEM3>>>(
        Eh, El, QKTh, QKTl, qf, qh, ql, D_MODEL, D_MODEL);
    // 2) scores ~= q @ E^T : 1-term approx, causal tile-skip
    gemm_hmma<1,0,1><<<dim3(N_CTX / 128, N_CTX / 128), 256, SMEM1>>>(
        qh, nullptr, Eh, nullptr, scores, nullptr, nullptr, N_CTX, D_MODEL);
    // 3) softmax with exact near-max recompute, split fp16 out
    softmax_rc<<<N_CTX, 256>>>(scores, qf, emb, Ph, Pl);
    // 4) ctx = P @ E : 3-term, k-truncated, split out
    gemm_hmma<2,1,3><<<dim3(D_MODEL / 128, N_CTX / 128), 256, SMEM3>>>(
        Ph, Pl, ETh, ETl, nullptr, cth, ctl, D_MODEL, N_CTX);
    // 5) out = ctx @ OV : 3-term, fp32 out
    gemm_hmma<0,0,3><<<dim3(D_MODEL / 128, N_CTX / 128), 256, SMEM3>>>(
        cth, ctl, OVTh, OVTl, out, nullptr, nullptr, D_MODEL, D_MODEL);
}

// round 7
// speedup vs baseline: 3.5342x; 1.1914x over previous
#include <cuda_runtime.h>
#include <cuda_fp16.h>
#include <cstdint>
#include <cstddef>

#define N_CTX 4096
#define D_MODEL 2048

// ---------------- scratch (__device__ globals; allocation-free) ----------------
__device__ __half g_Eh [(size_t)N_CTX * D_MODEL], g_El [(size_t)N_CTX * D_MODEL];
__device__ __half g_QKTh[(size_t)D_MODEL * D_MODEL], g_QKTl[(size_t)D_MODEL * D_MODEL];
__device__ __half g_ETh[(size_t)D_MODEL * N_CTX], g_ETl[(size_t)D_MODEL * N_CTX];
__device__ __half g_OVTh[(size_t)D_MODEL * D_MODEL], g_OVTl[(size_t)D_MODEL * D_MODEL];
__device__ __half g_qh [(size_t)N_CTX * D_MODEL], g_ql [(size_t)N_CTX * D_MODEL];
__device__ float  g_qf [(size_t)N_CTX * D_MODEL];
__device__ float  g_scores[(size_t)N_CTX * N_CTX];
__device__ __half g_Ph [(size_t)N_CTX * N_CTX], g_Pl [(size_t)N_CTX * N_CTX];
__device__ __half g_cth[(size_t)N_CTX * D_MODEL], g_ctl[(size_t)N_CTX * D_MODEL];

// ---------------- PTX helpers (baseline ISA; no tcgen05) ----------------
__device__ __forceinline__ uint32_t s2u(const void* p) {
    uint32_t a;
    asm("{ .reg .u64 t; cvta.to.shared.u64 t, %1; cvt.u32.u64 %0, t; }" : "=r"(a) : "l"(p));
    return a;
}
__device__ __forceinline__ void cp16(uint32_t d, const void* s) {
    asm volatile("cp.async.cg.shared.global [%0], [%1], 16;" :: "r"(d), "l"(s) : "memory");
}
__device__ __forceinline__ void cp_commit() { asm volatile("cp.async.commit_group;" ::: "memory"); }
__device__ __forceinline__ void cp_wait1()  { asm volatile("cp.async.wait_group 1;" ::: "memory"); }
__device__ __forceinline__ void cp_wait0()  { asm volatile("cp.async.wait_group 0;" ::: "memory"); }
__device__ __forceinline__ void ldmx4(uint32_t& r0, uint32_t& r1, uint32_t& r2, uint32_t& r3, uint32_t a) {
    asm volatile("ldmatrix.sync.aligned.m8n8.x4.shared.b16 {%0,%1,%2,%3}, [%4];"
                 : "=r"(r0), "=r"(r1), "=r"(r2), "=r"(r3) : "r"(a));
}
__device__ __forceinline__ void mma16816(float* c, const uint32_t* a, uint32_t b0, uint32_t b1) {
    asm volatile(
        "mma.sync.aligned.m16n8k16.row.col.f32.f16.f16.f32 "
        "{%0,%1,%2,%3}, {%4,%5,%6,%7}, {%8,%9}, {%0,%1,%2,%3};"
        : "+f"(c[0]), "+f"(c[1]), "+f"(c[2]), "+f"(c[3])
        : "r"(a[0]), "r"(a[1]), "r"(a[2]), "r"(a[3]), "r"(b0), "r"(b1));
}

// ---------------- tile loader: 128 rows x 64 halves, XOR-swizzled 128B rows ----------------
__device__ __forceinline__ void ld_tile(uint32_t dst, const __half* __restrict__ src,
                                        int row0, int kbase, int K, int tid)
{
    const int r  = tid >> 1;
    const int cb = (tid & 1) * 4;
    const __half* g = src + (size_t)(row0 + r) * K + kbase;
    const uint32_t rowoff = dst + r * 128;
    const int rx = r & 7;
    #pragma unroll
    for (int c = 0; c < 4; c++) {
        const int ch = cb + c;
        cp16(rowoff + ((ch ^ rx) << 4), g + ch * 8);
    }
}

// TERMS==1: {Ah,Bh}  TERMS==2: {Ah,Al,Bh}  TERMS==3: {Ah,Al,Bh,Bl}
template<int TERMS>
__device__ __forceinline__ void ld_stage(uint32_t st,
    const __half* Ah, const __half* Al, const __half* Bh, const __half* Bl,
    int rowBase, int colBase, int kbase, int K, int tid)
{
    constexpr uint32_t AB = (TERMS >= 2) ? 32768u : 16384u;
    ld_tile(st, Ah, rowBase, kbase, K, tid);
    if (TERMS >= 2) ld_tile(st + 16384, Al, rowBase, kbase, K, tid);
    ld_tile(st + AB, Bh, colBase, kbase, K, tid);
    if (TERMS == 3) ld_tile(st + AB + 16384, Bl, colBase, kbase, K, tid);
    cp_commit();
}

// ---------------- split-fp16 HMMA GEMM: C[M,N] = A[M,K] @ B[N,K]^T ----------------
// TERMS: 3 = AhBh+AhBl+AlBh ; 2 = AhBh+AlBh ; 1 = AhBh.
// MODE: 0 dense, 1 causal tile-skip, 2 k-truncated.
// SPLITOUT: 0 fp32 C ; 1 split fp16 C ; 2 both.
template<int MODE, int SPLITOUT, int TERMS>
__global__ __launch_bounds__(256) void gemm_hmma(
    const __half* __restrict__ Ah, const __half* __restrict__ Al,
    const __half* __restrict__ Bh, const __half* __restrict__ Bl,
    float* __restrict__ Cf, __half* __restrict__ Ch, __half* __restrict__ Cl,
    int N, int K)
{
    constexpr uint32_t AB = (TERMS >= 2) ? 32768u : 16384u;
    constexpr uint32_t SB = (TERMS == 3) ? 65536u : ((TERMS == 2) ? 49152u : 32768u);

    const int rowBase = blockIdx.y * 128;
    const int colBase = blockIdx.x * 128;
    if (MODE == 1 && colBase > rowBase) return;
    const int kEnd = (MODE == 2) ? (rowBase + 128) : K;
    const int T = kEnd >> 6;

    extern __shared__ char smraw[];
    const uint32_t sb = (s2u(smraw) + 127) & ~127u;
    const int tid = threadIdx.x;

    ld_stage<TERMS>(sb,      Ah, Al, Bh, Bl, rowBase, colBase, 0,  K, tid);
    ld_stage<TERMS>(sb + SB, Ah, Al, Bh, Bl, rowBase, colBase, 64, K, tid);

    const int warp = tid >> 5, lane = tid & 31;
    const int wM = (warp & 3) * 32;
    const int wN = (warp >> 2) * 64;

    float acc[2][8][4];
    #pragma unroll
    for (int mt = 0; mt < 2; mt++)
        #pragma unroll
        for (int n = 0; n < 8; n++)
            #pragma unroll
            for (int j = 0; j < 4; j++) acc[mt][n][j] = 0.f;

    const int aRowOff = (lane & 7) + (lane & 8);
    const int aChOff  = (lane >> 4) & 1;
    const int bRowOff = (lane & 7) + ((lane & 16) >> 1);
    const int bChOff  = (lane >> 3) & 1;

    for (int it = 0; it < T; it++) {
        if (it < T - 1) cp_wait1(); else cp_wait0();
        __syncthreads();
        if (it + 2 < T)
            ld_stage<TERMS>(sb + ((it + 2) % 3) * SB, Ah, Al, Bh, Bl,
                            rowBase, colBase, (it + 2) << 6, K, tid);

        const uint32_t stA = sb + (it % 3) * SB;
        const uint32_t stB = stA + AB;

        #pragma unroll
        for (int kk = 0; kk < 4; kk++) {
            uint32_t aH[2][4], aL[2][4];
            #pragma unroll
            for (int mt = 0; mt < 2; mt++) {
                const int r  = wM + mt * 16 + aRowOff;
                const int ch = 2 * kk + aChOff;
                const uint32_t off = r * 128 + ((ch ^ (r & 7)) << 4);
                ldmx4(aH[mt][0], aH[mt][1], aH[mt][2], aH[mt][3], stA + off);
                if (TERMS >= 2)
                    ldmx4(aL[mt][0], aL[mt][1], aL[mt][2], aL[mt][3], stA + 16384 + off);
            }
            #pragma unroll
            for (int nt = 0; nt < 4; nt++) {
                const int r  = wN + nt * 16 + bRowOff;
                const int ch = 2 * kk + bChOff;
                const uint32_t off = r * 128 + ((ch ^ (r & 7)) << 4);
                uint32_t h0, h1, h2, h3;
                ldmx4(h0, h1, h2, h3, stB + off);
                #pragma unroll
                for (int mt = 0; mt < 2; mt++) {
                    mma16816(acc[mt][nt * 2],     aH[mt], h0, h1);
                    mma16816(acc[mt][nt * 2 + 1], aH[mt], h2, h3);
                    if (TERMS >= 2) {
                        mma16816(acc[mt][nt * 2],     aL[mt], h0, h1);
                        mma16816(acc[mt][nt * 2 + 1], aL[mt], h2, h3);
                    }
                }
                if (TERMS == 3) {
                    uint32_t l0, l1, l2, l3;
                    ldmx4(l0, l1, l2, l3, stB + 16384 + off);
                    #pragma unroll
                    for (int mt = 0; mt < 2; mt++) {
                        mma16816(acc[mt][nt * 2],     aH[mt], l0, l1);
                        mma16816(acc[mt][nt * 2 + 1], aH[mt], l2, l3);
                    }
                }
            }
        }
    }

    // ---------------- epilogue ----------------
    const int g  = lane >> 2;
    const int t4 = lane & 3;
    #pragma unroll
    for (int mt = 0; mt < 2; mt++) {
        const int row0 = rowBase + wM + mt * 16 + g;
        #pragma unroll
        for (int n = 0; n < 8; n++) {
            const int col = colBase + wN + n * 8 + t4 * 2;
            if (SPLITOUT == 0 || SPLITOUT == 2) {
                *(float2*)(Cf + (size_t)row0 * N + col) =
                    make_float2(acc[mt][n][0], acc[mt][n][1]);
                *(float2*)(Cf + (size_t)(row0 + 8) * N + col) =
                    make_float2(acc[mt][n][2], acc[mt][n][3]);
            }
            if (SPLITOUT >= 1) {
                #pragma unroll
                for (int hrow = 0; hrow < 2; hrow++) {
                    const float v0 = acc[mt][n][hrow * 2], v1 = acc[mt][n][hrow * 2 + 1];
                    const __half h0 = __float2half(v0), h1 = __float2half(v1);
                    const size_t o = (size_t)(row0 + hrow * 8) * N + col;
                    *(__half2*)(Ch + o) = __halves2half2(h0, h1);
                    *(__half2*)(Cl + o) = __halves2half2(
                        __float2half(v0 - __half2float(h0)),
                        __float2half(v1 - __half2float(h1)));
                }
            }
        }
    }
}

// ---------------- fp32 -> (hi,lo) fp16 split ----------------
__global__ __launch_bounds__(256) void split_rm(const float* __restrict__ X,
                                                __half* __restrict__ H, __half* __restrict__ L, int n4)
{
    int i = blockIdx.x * 256 + threadIdx.x;
    if (i >= n4) return;
    float4 v = ((const float4*)X)[i];
    float vs[4] = {v.x, v.y, v.z, v.w};
    __half h[4], l[4];
    #pragma unroll
    for (int j = 0; j < 4; j++) {
        h[j] = __float2half(vs[j]);
        l[j] = __float2half(vs[j] - __half2float(h[j]));
    }
    ((__half2*)H)[2 * i]     = __halves2half2(h[0], h[1]);
    ((__half2*)H)[2 * i + 1] = __halves2half2(h[2], h[3]);
    ((__half2*)L)[2 * i]     = __halves2half2(l[0], l[1]);
    ((__half2*)L)[2 * i + 1] = __halves2half2(l[2], l[3]);
}

// ---------------- fp32 [R,C] -> transposed (hi,lo) fp16 [C,R] ----------------
__global__ __launch_bounds__(256) void tsplit(const float* __restrict__ X,
                                              __half* __restrict__ H, __half* __restrict__ L, int R, int C)
{
    __shared__ float tile[32][33];
    const int tx = threadIdx.x, ty = threadIdx.y;
    const int c0 = blockIdx.x * 32, r0 = blockIdx.y * 32;
    #pragma unroll
    for (int i = 0; i < 32; i += 8)
        tile[ty + i][tx] = X[(size_t)(r0 + ty + i) * C + c0 + tx];
    __syncthreads();
    #pragma unroll
    for (int i = 0; i < 32; i += 8) {
        float v = tile[tx][ty + i];
        __half h = __float2half(v);
        size_t o = (size_t)(c0 + ty + i) * R + r0 + tx;
        H[o] = h;
        L[o] = __float2half(v - __half2float(h));
    }
}

// ---------------- causal softmax with exact recompute of near-max entries ----------------
#define RC_MARGIN 20.0f
#define RC_CAP 1024
__global__ __launch_bounds__(256) void softmax_rc(const float* __restrict__ S,
                                                  const float* __restrict__ qf,
                                                  const float* __restrict__ emb,
                                                  __half* __restrict__ Ph, __half* __restrict__ Pl)
{
    __shared__ float buf[N_CTX];
    __shared__ float red[256];
    __shared__ int   list[RC_CAP];
    __shared__ int   cnt;
    const int i = blockIdx.x, t = threadIdx.x;
    const int n = i + 1;
    const float* row = S + (size_t)i * N_CTX;

    float m = -3.0e38f;
    for (int j = t; j < n; j += 256) { float v = row[j]; buf[j] = v; m = fmaxf(m, v); }
    red[t] = m;
    if (t == 0) cnt = 0;
    __syncthreads();
    for (int s2 = 128; s2 > 0; s2 >>= 1) {
        if (t < s2) red[t] = fmaxf(red[t], red[t + s2]);
        __syncthreads();
    }
    m = red[0];
    __syncthreads();

    for (int j = t; j < n; j += 256)
        if (buf[j] > m - RC_MARGIN) {
            int p = atomicAdd(&cnt, 1);
            if (p < RC_CAP) list[p] = j;
        }
    __syncthreads();
    const int nc = min(cnt, RC_CAP);

    const int warp = t >> 5, lane = t & 31;
    const float4* qp = (const float4*)(qf + (size_t)i * D_MODEL);
    for (int c = warp; c < nc; c += 8) {
        const int j = list[c];
        const float4* ep = (const float4*)(emb + (size_t)j * D_MODEL);
        float s = 0.f;
        #pragma unroll 4
        for (int k = lane; k < D_MODEL / 4; k += 32) {
            float4 a = qp[k], b = ep[k];
            s += a.x * b.x + a.y * b.y + a.z * b.z + a.w * b.w;
        }
        #pragma unroll
        for (int off = 16; off > 0; off >>= 1) s += __shfl_xor_sync(0xFFFFFFFFu, s, off);
        if (lane == 0) buf[j] = s;
    }
    __syncthreads();

    m = -3.0e38f;
    for (int j = t; j < n; j += 256) m = fmaxf(m, buf[j]);
    red[t] = m;
    __syncthreads();
    for (int s2 = 128; s2 > 0; s2 >>= 1) {
        if (t < s2) red[t] = fmaxf(red[t], red[t + s2]);
        __syncthreads();
    }
    m = red[0];
    __syncthreads();

    float s = 0.f;
    for (int j = t; j < n; j += 256) { float e = expf(buf[j] - m); buf[j] = e; s += e; }
    red[t] = s;
    __syncthreads();
    for (int s2 = 128; s2 > 0; s2 >>= 1) {
        if (t < s2) red[t] += red[t + s2];
        __syncthreads();
    }
    const float inv = 1.0f / red[0];

    const int zEnd = ((i >> 7) + 1) << 7;
    for (int j = t; j < zEnd; j += 256) {
        float p = (j < n) ? buf[j] * inv : 0.0f;
        __half h = __float2half(p);
        const size_t o = (size_t)i * N_CTX + j;
        Ph[o] = h;
        Pl[o] = __float2half(p - __half2float(h));
    }
}

// ---------------------------------------------------------------------------
extern "C" void kernel_launch(void* const* d_in, const int* in_sizes, int n_in,
                              void* d_out, int out_size)
{
    const float* emb = (const float*)d_in[0];   // [4096, 2048]
    const float* qk  = (const float*)d_in[1];   // [2048, 2048]
    const float* ov  = (const float*)d_in[2];   // [2048, 2048]
    float* out = (float*)d_out;                 // [4096, 2048]

    __half *Eh, *El, *QKTh, *QKTl, *ETh, *ETl, *OVTh, *OVTl, *qh, *ql, *Ph, *Pl, *cth, *ctl;
    float *scores, *qf;
    cudaGetSymbolAddress((void**)&Eh, g_Eh);     cudaGetSymbolAddress((void**)&El, g_El);
    cudaGetSymbolAddress((void**)&QKTh, g_QKTh); cudaGetSymbolAddress((void**)&QKTl, g_QKTl);
    cudaGetSymbolAddress((void**)&ETh, g_ETh);   cudaGetSymbolAddress((void**)&ETl, g_ETl);
    cudaGetSymbolAddress((void**)&OVTh, g_OVTh); cudaGetSymbolAddress((void**)&OVTl, g_OVTl);
    cudaGetSymbolAddress((void**)&qh, g_qh);     cudaGetSymbolAddress((void**)&ql, g_ql);
    cudaGetSymbolAddress((void**)&Ph, g_Ph);     cudaGetSymbolAddress((void**)&Pl, g_Pl);
    cudaGetSymbolAddress((void**)&cth, g_cth);   cudaGetSymbolAddress((void**)&ctl, g_ctl);
    cudaGetSymbolAddress((void**)&scores, g_scores);
    cudaGetSymbolAddress((void**)&qf, g_qf);

    const int SMEM3 = 3 * 65536 + 128;
    const int SMEM2 = 3 * 49152 + 128;
    const int SMEM1 = 3 * 32768 + 128;
    cudaFuncSetAttribute(gemm_hmma<0,2,3>, cudaFuncAttributeMaxDynamicSharedMemorySize, SMEM3);
    cudaFuncSetAttribute(gemm_hmma<1,0,1>, cudaFuncAttributeMaxDynamicSharedMemorySize, SMEM1);
    cudaFuncSetAttribute(gemm_hmma<2,1,2>, cudaFuncAttributeMaxDynamicSharedMemorySize, SMEM2);
    cudaFuncSetAttribute(gemm_hmma<0,0,2>, cudaFuncAttributeMaxDynamicSharedMemorySize, SMEM2);

    // operand prep
    split_rm<<<(N_CTX * D_MODEL / 4 + 255) / 256, 256>>>(emb, Eh, El, N_CTX * D_MODEL / 4);
    tsplit<<<dim3(D_MODEL / 32, D_MODEL / 32), dim3(32, 8)>>>(qk, QKTh, QKTl, D_MODEL, D_MODEL);
    tsplit<<<dim3(D_MODEL / 32, D_MODEL / 32), dim3(32, 8)>>>(ov, OVTh, OVTl, D_MODEL, D_MODEL);
    tsplit<<<dim3(D_MODEL / 32, N_CTX / 32), dim3(32, 8)>>>(emb, ETh, ETl, N_CTX, D_MODEL);

    // 1) q = E @ QK : 3-term, split fp16 + fp32 out
    gemm_hmma<0,2,3><<<dim3(D_MODEL / 128, N_CTX / 128), 256, SMEM3>>>(
        Eh, El, QKTh, QKTl, qf, qh, ql, D_MODEL, D_MODEL);
    // 2) scores ~= q @ E^T : 1-term approx, causal tile-skip
    gemm_hmma<1,0,1><<<dim3(N_CTX / 128, N_CTX / 128), 256, SMEM1>>>(
        qh, nullptr, Eh, nullptr, scores, nullptr, nullptr, N_CTX, D_MODEL);
    // 3) softmax with exact near-max recompute, split fp16 out
    softmax_rc<<<N_CTX, 256>>>(scores, qf, emb, Ph, Pl);
    // 4) ctx = P @ E : 2-term (P full split x Eh), k-truncated, split out
    gemm_hmma<2,1,2><<<dim3(D_MODEL / 128, N_CTX / 128), 256, SMEM2>>>(
        Ph, Pl, ETh, nullptr, nullptr, cth, ctl, D_MODEL, N_CTX);
    // 5) out = ctx @ OV : 2-term (ct full split x OVh), fp32 out
    gemm_hmma<0,0,2><<<dim3(D_MODEL / 128, N_CTX / 128), 256, SMEM2>>>(
        cth, ctl, OVTh, nullptr, out, nullptr, nullptr, D_MODEL, D_MODEL);
}

// round 8
// speedup vs baseline: 4.6249x; 1.3086x over previous
#include <cuda_runtime.h>
#include <cuda_fp16.h>
#include <cstdint>
#include <cstddef>

#define N_CTX 4096
#define D_MODEL 2048

// ---------------- scratch (__device__ globals; allocation-free) ----------------
__device__ __half g_Eh [(size_t)N_CTX * D_MODEL], g_El [(size_t)N_CTX * D_MODEL];
__device__ __half g_QKTh[(size_t)D_MODEL * D_MODEL], g_QKTl[(size_t)D_MODEL * D_MODEL];
__device__ __half g_ETh[(size_t)D_MODEL * N_CTX];
__device__ __half g_OVTh[(size_t)D_MODEL * D_MODEL];
__device__ __half g_qh [(size_t)N_CTX * D_MODEL], g_ql [(size_t)N_CTX * D_MODEL];
__device__ float  g_qf [(size_t)N_CTX * D_MODEL];
__device__ float  g_scores[(size_t)N_CTX * N_CTX];
__device__ __half g_Ph [(size_t)N_CTX * N_CTX];
__device__ __half g_cth[(size_t)N_CTX * D_MODEL];

// ---------------- PTX helpers (baseline ISA; no tcgen05) ----------------
__device__ __forceinline__ uint32_t s2u(const void* p) {
    uint32_t a;
    asm("{ .reg .u64 t; cvta.to.shared.u64 t, %1; cvt.u32.u64 %0, t; }" : "=r"(a) : "l"(p));
    return a;
}
__device__ __forceinline__ void cp16(uint32_t d, const void* s) {
    asm volatile("cp.async.cg.shared.global [%0], [%1], 16;" :: "r"(d), "l"(s) : "memory");
}
__device__ __forceinline__ void cp_commit() { asm volatile("cp.async.commit_group;" ::: "memory"); }
__device__ __forceinline__ void cp_wait1()  { asm volatile("cp.async.wait_group 1;" ::: "memory"); }
__device__ __forceinline__ void cp_wait0()  { asm volatile("cp.async.wait_group 0;" ::: "memory"); }
__device__ __forceinline__ void ldmx4(uint32_t& r0, uint32_t& r1, uint32_t& r2, uint32_t& r3, uint32_t a) {
    asm volatile("ldmatrix.sync.aligned.m8n8.x4.shared.b16 {%0,%1,%2,%3}, [%4];"
                 : "=r"(r0), "=r"(r1), "=r"(r2), "=r"(r3) : "r"(a));
}
__device__ __forceinline__ void mma16816(float* c, const uint32_t* a, uint32_t b0, uint32_t b1) {
    asm volatile(
        "mma.sync.aligned.m16n8k16.row.col.f32.f16.f16.f32 "
        "{%0,%1,%2,%3}, {%4,%5,%6,%7}, {%8,%9}, {%0,%1,%2,%3};"
        : "+f"(c[0]), "+f"(c[1]), "+f"(c[2]), "+f"(c[3])
        : "r"(a[0]), "r"(a[1]), "r"(a[2]), "r"(a[3]), "r"(b0), "r"(b1));
}

// ---------------- tile loader: 128 rows x 64 halves, XOR-swizzled 128B rows ----------------
__device__ __forceinline__ void ld_tile(uint32_t dst, const __half* __restrict__ src,
                                        int row0, int kbase, int K, int tid)
{
    const int r  = tid >> 1;
    const int cb = (tid & 1) * 4;
    const __half* g = src + (size_t)(row0 + r) * K + kbase;
    const uint32_t rowoff = dst + r * 128;
    const int rx = r & 7;
    #pragma unroll
    for (int c = 0; c < 4; c++) {
        const int ch = cb + c;
        cp16(rowoff + ((ch ^ rx) << 4), g + ch * 8);
    }
}

// TERMS==1: {Ah,Bh}  TERMS==2: {Ah,Al,Bh}  TERMS==3: {Ah,Al,Bh,Bl}
template<int TERMS>
__device__ __forceinline__ void ld_stage(uint32_t st,
    const __half* Ah, const __half* Al, const __half* Bh, const __half* Bl,
    int rowBase, int colBase, int kbase, int K, int tid)
{
    constexpr uint32_t AB = (TERMS >= 2) ? 32768u : 16384u;
    ld_tile(st, Ah, rowBase, kbase, K, tid);
    if (TERMS >= 2) ld_tile(st + 16384, Al, rowBase, kbase, K, tid);
    ld_tile(st + AB, Bh, colBase, kbase, K, tid);
    if (TERMS == 3) ld_tile(st + AB + 16384, Bl, colBase, kbase, K, tid);
    cp_commit();
}

// ---------------- split-fp16 HMMA GEMM: C[M,N] = A[M,K] @ B[N,K]^T ----------------
// TERMS: 3 = AhBh+AhBl+AlBh ; 2 = AhBh+AlBh ; 1 = AhBh.
// MODE: 0 dense, 1 causal tile-skip, 2 k-truncated.
// SPLITOUT: 0 fp32 C ; 1 split fp16 C ; 2 fp32+split ; 3 hi fp16 only.
template<int MODE, int SPLITOUT, int TERMS>
__global__ __launch_bounds__(256) void gemm_hmma(
    const __half* __restrict__ Ah, const __half* __restrict__ Al,
    const __half* __restrict__ Bh, const __half* __restrict__ Bl,
    float* __restrict__ Cf, __half* __restrict__ Ch, __half* __restrict__ Cl,
    int N, int K)
{
    constexpr uint32_t AB = (TERMS >= 2) ? 32768u : 16384u;
    constexpr uint32_t SB = (TERMS == 3) ? 65536u : ((TERMS == 2) ? 49152u : 32768u);

    const int rowBase = blockIdx.y * 128;
    const int colBase = blockIdx.x * 128;
    if (MODE == 1 && colBase > rowBase) return;
    const int kEnd = (MODE == 2) ? (rowBase + 128) : K;
    const int T = kEnd >> 6;

    extern __shared__ char smraw[];
    const uint32_t sb = (s2u(smraw) + 127) & ~127u;
    const int tid = threadIdx.x;

    ld_stage<TERMS>(sb,      Ah, Al, Bh, Bl, rowBase, colBase, 0,  K, tid);
    ld_stage<TERMS>(sb + SB, Ah, Al, Bh, Bl, rowBase, colBase, 64, K, tid);

    const int warp = tid >> 5, lane = tid & 31;
    const int wM = (warp & 3) * 32;
    const int wN = (warp >> 2) * 64;

    float acc[2][8][4];
    #pragma unroll
    for (int mt = 0; mt < 2; mt++)
        #pragma unroll
        for (int n = 0; n < 8; n++)
            #pragma unroll
            for (int j = 0; j < 4; j++) acc[mt][n][j] = 0.f;

    const int aRowOff = (lane & 7) + (lane & 8);
    const int aChOff  = (lane >> 4) & 1;
    const int bRowOff = (lane & 7) + ((lane & 16) >> 1);
    const int bChOff  = (lane >> 3) & 1;

    for (int it = 0; it < T; it++) {
        if (it < T - 1) cp_wait1(); else cp_wait0();
        __syncthreads();
        if (it + 2 < T)
            ld_stage<TERMS>(sb + ((it + 2) % 3) * SB, Ah, Al, Bh, Bl,
                            rowBase, colBase, (it + 2) << 6, K, tid);

        const uint32_t stA = sb + (it % 3) * SB;
        const uint32_t stB = stA + AB;

        #pragma unroll
        for (int kk = 0; kk < 4; kk++) {
            uint32_t aH[2][4], aL[2][4];
            #pragma unroll
            for (int mt = 0; mt < 2; mt++) {
                const int r  = wM + mt * 16 + aRowOff;
                const int ch = 2 * kk + aChOff;
                const uint32_t off = r * 128 + ((ch ^ (r & 7)) << 4);
                ldmx4(aH[mt][0], aH[mt][1], aH[mt][2], aH[mt][3], stA + off);
                if (TERMS >= 2)
                    ldmx4(aL[mt][0], aL[mt][1], aL[mt][2], aL[mt][3], stA + 16384 + off);
            }
            #pragma unroll
            for (int nt = 0; nt < 4; nt++) {
                const int r  = wN + nt * 16 + bRowOff;
                const int ch = 2 * kk + bChOff;
                const uint32_t off = r * 128 + ((ch ^ (r & 7)) << 4);
                uint32_t h0, h1, h2, h3;
                ldmx4(h0, h1, h2, h3, stB + off);
                #pragma unroll
                for (int mt = 0; mt < 2; mt++) {
                    mma16816(acc[mt][nt * 2],     aH[mt], h0, h1);
                    mma16816(acc[mt][nt * 2 + 1], aH[mt], h2, h3);
                    if (TERMS >= 2) {
                        mma16816(acc[mt][nt * 2],     aL[mt], h0, h1);
                        mma16816(acc[mt][nt * 2 + 1], aL[mt], h2, h3);
                    }
                }
                if (TERMS == 3) {
                    uint32_t l0, l1, l2, l3;
                    ldmx4(l0, l1, l2, l3, stB + 16384 + off);
                    #pragma unroll
                    for (int mt = 0; mt < 2; mt++) {
                        mma16816(acc[mt][nt * 2],     aH[mt], l0, l1);
                        mma16816(acc[mt][nt * 2 + 1], aH[mt], l2, l3);
                    }
                }
            }
        }
    }

    // ---------------- epilogue ----------------
    const int g  = lane >> 2;
    const int t4 = lane & 3;
    #pragma unroll
    for (int mt = 0; mt < 2; mt++) {
        const int row0 = rowBase + wM + mt * 16 + g;
        #pragma unroll
        for (int n = 0; n < 8; n++) {
            const int col = colBase + wN + n * 8 + t4 * 2;
            if (SPLITOUT == 0 || SPLITOUT == 2) {
                *(float2*)(Cf + (size_t)row0 * N + col) =
                    make_float2(acc[mt][n][0], acc[mt][n][1]);
                *(float2*)(Cf + (size_t)(row0 + 8) * N + col) =
                    make_float2(acc[mt][n][2], acc[mt][n][3]);
            }
            if (SPLITOUT == 1 || SPLITOUT == 2) {
                #pragma unroll
                for (int hrow = 0; hrow < 2; hrow++) {
                    const float v0 = acc[mt][n][hrow * 2], v1 = acc[mt][n][hrow * 2 + 1];
                    const __half h0 = __float2half(v0), h1 = __float2half(v1);
                    const size_t o = (size_t)(row0 + hrow * 8) * N + col;
                    *(__half2*)(Ch + o) = __halves2half2(h0, h1);
                    *(__half2*)(Cl + o) = __halves2half2(
                        __float2half(v0 - __half2float(h0)),
                        __float2half(v1 - __half2float(h1)));
                }
            }
            if (SPLITOUT == 3) {
                #pragma unroll
                for (int hrow = 0; hrow < 2; hrow++) {
                    const size_t o = (size_t)(row0 + hrow * 8) * N + col;
                    *(__half2*)(Ch + o) = __halves2half2(
                        __float2half(acc[mt][n][hrow * 2]),
                        __float2half(acc[mt][n][hrow * 2 + 1]));
                }
            }
        }
    }
}

// ---------------- fp32 -> (hi,lo) fp16 split ----------------
__global__ __launch_bounds__(256) void split_rm(const float* __restrict__ X,
                                                __half* __restrict__ H, __half* __restrict__ L, int n4)
{
    int i = blockIdx.x * 256 + threadIdx.x;
    if (i >= n4) return;
    float4 v = ((const float4*)X)[i];
    float vs[4] = {v.x, v.y, v.z, v.w};
    __half h[4], l[4];
    #pragma unroll
    for (int j = 0; j < 4; j++) {
        h[j] = __float2half(vs[j]);
        l[j] = __float2half(vs[j] - __half2float(h[j]));
    }
    ((__half2*)H)[2 * i]     = __halves2half2(h[0], h[1]);
    ((__half2*)H)[2 * i + 1] = __halves2half2(h[2], h[3]);
    ((__half2*)L)[2 * i]     = __halves2half2(l[0], l[1]);
    ((__half2*)L)[2 * i + 1] = __halves2half2(l[2], l[3]);
}

// ---------------- fp32 [R,C] -> transposed fp16 [C,R]; L optional ----------------
__global__ __launch_bounds__(256) void tsplit(const float* __restrict__ X,
                                              __half* __restrict__ H, __half* __restrict__ L, int R, int C)
{
    __shared__ float tile[32][33];
    const int tx = threadIdx.x, ty = threadIdx.y;
    const int c0 = blockIdx.x * 32, r0 = blockIdx.y * 32;
    #pragma unroll
    for (int i = 0; i < 32; i += 8)
        tile[ty + i][tx] = X[(size_t)(r0 + ty + i) * C + c0 + tx];
    __syncthreads();
    #pragma unroll
    for (int i = 0; i < 32; i += 8) {
        float v = tile[tx][ty + i];
        __half h = __float2half(v);
        size_t o = (size_t)(c0 + ty + i) * R + r0 + tx;
        H[o] = h;
        if (L) L[o] = __float2half(v - __half2float(h));
    }
}

// ---------------- causal softmax with exact recompute of near-max entries ----------------
#define RC_MARGIN 20.0f
#define RC_CAP 1024
__global__ __launch_bounds__(256) void softmax_rc(const float* __restrict__ S,
                                                  const float* __restrict__ qf,
                                                  const float* __restrict__ emb,
                                                  __half* __restrict__ Ph)
{
    __shared__ float buf[N_CTX];
    __shared__ float red[256];
    __shared__ int   list[RC_CAP];
    __shared__ int   cnt;
    const int i = blockIdx.x, t = threadIdx.x;
    const int n = i + 1;
    const float* row = S + (size_t)i * N_CTX;

    float m = -3.0e38f;
    for (int j = t; j < n; j += 256) { float v = row[j]; buf[j] = v; m = fmaxf(m, v); }
    red[t] = m;
    if (t == 0) cnt = 0;
    __syncthreads();
    for (int s2 = 128; s2 > 0; s2 >>= 1) {
        if (t < s2) red[t] = fmaxf(red[t], red[t + s2]);
        __syncthreads();
    }
    m = red[0];
    __syncthreads();

    for (int j = t; j < n; j += 256)
        if (buf[j] > m - RC_MARGIN) {
            int p = atomicAdd(&cnt, 1);
            if (p < RC_CAP) list[p] = j;
        }
    __syncthreads();
    const int nc = min(cnt, RC_CAP);

    const int warp = t >> 5, lane = t & 31;
    const float4* qp = (const float4*)(qf + (size_t)i * D_MODEL);
    for (int c = warp; c < nc; c += 8) {
        const int j = list[c];
        const float4* ep = (const float4*)(emb + (size_t)j * D_MODEL);
        float s = 0.f;
        #pragma unroll 4
        for (int k = lane; k < D_MODEL / 4; k += 32) {
            float4 a = qp[k], b = ep[k];
            s += a.x * b.x + a.y * b.y + a.z * b.z + a.w * b.w;
        }
        #pragma unroll
        for (int off = 16; off > 0; off >>= 1) s += __shfl_xor_sync(0xFFFFFFFFu, s, off);
        if (lane == 0) buf[j] = s;
    }
    __syncthreads();

    m = -3.0e38f;
    for (int j = t; j < n; j += 256) m = fmaxf(m, buf[j]);
    red[t] = m;
    __syncthreads();
    for (int s2 = 128; s2 > 0; s2 >>= 1) {
        if (t < s2) red[t] = fmaxf(red[t], red[t + s2]);
        __syncthreads();
    }
    m = red[0];
    __syncthreads();

    float s = 0.f;
    for (int j = t; j < n; j += 256) { float e = expf(buf[j] - m); buf[j] = e; s += e; }
    red[t] = s;
    __syncthreads();
    for (int s2 = 128; s2 > 0; s2 >>= 1) {
        if (t < s2) red[t] += red[t + s2];
        __syncthreads();
    }
    const float inv = 1.0f / red[0];

    const int zEnd = ((i >> 7) + 1) << 7;
    for (int j = t; j < zEnd; j += 256) {
        float p = (j < n) ? buf[j] * inv : 0.0f;
        Ph[(size_t)i * N_CTX + j] = __float2half(p);
    }
}

// ---------------------------------------------------------------------------
extern "C" void kernel_launch(void* const* d_in, const int* in_sizes, int n_in,
                              void* d_out, int out_size)
{
    const float* emb = (const float*)d_in[0];   // [4096, 2048]
    const float* qk  = (const float*)d_in[1];   // [2048, 2048]
    const float* ov  = (const float*)d_in[2];   // [2048, 2048]
    float* out = (float*)d_out;                 // [4096, 2048]

    __half *Eh, *El, *QKTh, *QKTl, *ETh, *OVTh, *qh, *ql, *Ph, *cth;
    float *scores, *qf;
    cudaGetSymbolAddress((void**)&Eh, g_Eh);     cudaGetSymbolAddress((void**)&El, g_El);
    cudaGetSymbolAddress((void**)&QKTh, g_QKTh); cudaGetSymbolAddress((void**)&QKTl, g_QKTl);
    cudaGetSymbolAddress((void**)&ETh, g_ETh);
    cudaGetSymbolAddress((void**)&OVTh, g_OVTh);
    cudaGetSymbolAddress((void**)&qh, g_qh);     cudaGetSymbolAddress((void**)&ql, g_ql);
    cudaGetSymbolAddress((void**)&Ph, g_Ph);
    cudaGetSymbolAddress((void**)&cth, g_cth);
    cudaGetSymbolAddress((void**)&scores, g_scores);
    cudaGetSymbolAddress((void**)&qf, g_qf);

    const int SMEM3 = 3 * 65536 + 128;
    const int SMEM1 = 3 * 32768 + 128;
    cudaFuncSetAttribute(gemm_hmma<0,2,3>, cudaFuncAttributeMaxDynamicSharedMemorySize, SMEM3);
    cudaFuncSetAttribute(gemm_hmma<1,0,1>, cudaFuncAttributeMaxDynamicSharedMemorySize, SMEM1);
    cudaFuncSetAttribute(gemm_hmma<2,3,1>, cudaFuncAttributeMaxDynamicSharedMemorySize, SMEM1);
    cudaFuncSetAttribute(gemm_hmma<0,0,1>, cudaFuncAttributeMaxDynamicSharedMemorySize, SMEM1);

    // operand prep
    split_rm<<<(N_CTX * D_MODEL / 4 + 255) / 256, 256>>>(emb, Eh, El, N_CTX * D_MODEL / 4);
    tsplit<<<dim3(D_MODEL / 32, D_MODEL / 32), dim3(32, 8)>>>(qk, QKTh, QKTl, D_MODEL, D_MODEL);
    tsplit<<<dim3(D_MODEL / 32, D_MODEL / 32), dim3(32, 8)>>>(ov, OVTh, nullptr, D_MODEL, D_MODEL);
    tsplit<<<dim3(D_MODEL / 32, N_CTX / 32), dim3(32, 8)>>>(emb, ETh, nullptr, N_CTX, D_MODEL);

    // 1) q = E @ QK : 3-term, split fp16 + fp32 out
    gemm_hmma<0,2,3><<<dim3(D_MODEL / 128, N_CTX / 128), 256, SMEM3>>>(
        Eh, El, QKTh, QKTl, qf, qh, ql, D_MODEL, D_MODEL);
    // 2) scores ~= q @ E^T : 1-term approx, causal tile-skip
    gemm_hmma<1,0,1><<<dim3(N_CTX / 128, N_CTX / 128), 256, SMEM1>>>(
        qh, nullptr, Eh, nullptr, scores, nullptr, nullptr, N_CTX, D_MODEL);
    // 3) softmax with exact near-max recompute, hi fp16 out
    softmax_rc<<<N_CTX, 256>>>(scores, qf, emb, Ph);
    // 4) ctx = P @ E : 1-term, k-truncated, hi fp16 out
    gemm_hmma<2,3,1><<<dim3(D_MODEL / 128, N_CTX / 128), 256, SMEM1>>>(
        Ph, nullptr, ETh, nullptr, nullptr, cth, nullptr, D_MODEL, N_CTX);
    // 5) out = ctx @ OV : 1-term, fp32 out
    gemm_hmma<0,0,1><<<dim3(D_MODEL / 128, N_CTX / 128), 256, SMEM1>>>(
        cth, nullptr, OVTh, nullptr, out, nullptr, nullptr, D_MODEL, D_MODEL);
}

// round 9
// speedup vs baseline: 5.6069x; 1.2123x over previous
#include <cuda_runtime.h>
#include <cuda_fp16.h>
#include <cstdint>
#include <cstddef>

#define N_CTX 4096
#define D_MODEL 2048

// ---------------- scratch (__device__ globals; allocation-free) ----------------
__device__ __half g_Eh [(size_t)N_CTX * D_MODEL], g_El [(size_t)N_CTX * D_MODEL];
__device__ __half g_QKTh[(size_t)D_MODEL * D_MODEL], g_QKTl[(size_t)D_MODEL * D_MODEL];
__device__ __half g_OVTh[(size_t)D_MODEL * D_MODEL];
__device__ __half g_qh [(size_t)N_CTX * D_MODEL];
__device__ float  g_qf [(size_t)N_CTX * D_MODEL];
__device__ float  g_scores[(size_t)N_CTX * N_CTX];
__device__ __half g_cth[(size_t)N_CTX * D_MODEL];

// ---------------- PTX helpers (baseline ISA; no tcgen05) ----------------
__device__ __forceinline__ uint32_t s2u(const void* p) {
    uint32_t a;
    asm("{ .reg .u64 t; cvta.to.shared.u64 t, %1; cvt.u32.u64 %0, t; }" : "=r"(a) : "l"(p));
    return a;
}
__device__ __forceinline__ void cp16(uint32_t d, const void* s) {
    asm volatile("cp.async.cg.shared.global [%0], [%1], 16;" :: "r"(d), "l"(s) : "memory");
}
__device__ __forceinline__ void cp_commit() { asm volatile("cp.async.commit_group;" ::: "memory"); }
__device__ __forceinline__ void cp_wait1()  { asm volatile("cp.async.wait_group 1;" ::: "memory"); }
__device__ __forceinline__ void cp_wait0()  { asm volatile("cp.async.wait_group 0;" ::: "memory"); }
__device__ __forceinline__ void ldmx4(uint32_t& r0, uint32_t& r1, uint32_t& r2, uint32_t& r3, uint32_t a) {
    asm volatile("ldmatrix.sync.aligned.m8n8.x4.shared.b16 {%0,%1,%2,%3}, [%4];"
                 : "=r"(r0), "=r"(r1), "=r"(r2), "=r"(r3) : "r"(a));
}
__device__ __forceinline__ void mma16816(float* c, const uint32_t* a, uint32_t b0, uint32_t b1) {
    asm volatile(
        "mma.sync.aligned.m16n8k16.row.col.f32.f16.f16.f32 "
        "{%0,%1,%2,%3}, {%4,%5,%6,%7}, {%8,%9}, {%0,%1,%2,%3};"
        : "+f"(c[0]), "+f"(c[1]), "+f"(c[2]), "+f"(c[3])
        : "r"(a[0]), "r"(a[1]), "r"(a[2]), "r"(a[3]), "r"(b0), "r"(b1));
}

// ---------------- tile loader: 128 rows x 64 halves, XOR-swizzled 128B rows ----------------
__device__ __forceinline__ void ld_tile(uint32_t dst, const __half* __restrict__ src,
                                        int row0, int kbase, int K, int tid)
{
    const int r  = tid >> 1;
    const int cb = (tid & 1) * 4;
    const __half* g = src + (size_t)(row0 + r) * K + kbase;
    const uint32_t rowoff = dst + r * 128;
    const int rx = r & 7;
    #pragma unroll
    for (int c = 0; c < 4; c++) {
        const int ch = cb + c;
        cp16(rowoff + ((ch ^ rx) << 4), g + ch * 8);
    }
}

// TERMS==1: {Ah,Bh}  TERMS==3: {Ah,Al,Bh,Bl}
template<int TERMS>
__device__ __forceinline__ void ld_stage(uint32_t st,
    const __half* Ah, const __half* Al, const __half* Bh, const __half* Bl,
    int rowBase, int colBase, int kbase, int K, int tid)
{
    constexpr uint32_t AB = (TERMS >= 2) ? 32768u : 16384u;
    ld_tile(st, Ah, rowBase, kbase, K, tid);
    if (TERMS >= 2) ld_tile(st + 16384, Al, rowBase, kbase, K, tid);
    ld_tile(st + AB, Bh, colBase, kbase, K, tid);
    if (TERMS == 3) ld_tile(st + AB + 16384, Bl, colBase, kbase, K, tid);
    cp_commit();
}

// ---------------- split-fp16 HMMA GEMM: C[M,N] = A[M,K] @ B[N,K]^T ----------------
// TERMS: 3 = AhBh+AhBl+AlBh ; 1 = AhBh.
// MODE: 0 dense, 1 causal tile-skip.
// SPLITOUT: 0 fp32 C ; 4 fp32 + hi fp16.
template<int MODE, int SPLITOUT, int TERMS>
__global__ __launch_bounds__(256) void gemm_hmma(
    const __half* __restrict__ Ah, const __half* __restrict__ Al,
    const __half* __restrict__ Bh, const __half* __restrict__ Bl,
    float* __restrict__ Cf, __half* __restrict__ Ch,
    int N, int K)
{
    constexpr uint32_t AB = (TERMS >= 2) ? 32768u : 16384u;
    constexpr uint32_t SB = (TERMS == 3) ? 65536u : 32768u;

    const int rowBase = blockIdx.y * 128;
    const int colBase = blockIdx.x * 128;
    if (MODE == 1 && colBase > rowBase) return;
    const int T = K >> 6;

    extern __shared__ char smraw[];
    const uint32_t sb = (s2u(smraw) + 127) & ~127u;
    const int tid = threadIdx.x;

    ld_stage<TERMS>(sb,      Ah, Al, Bh, Bl, rowBase, colBase, 0,  K, tid);
    ld_stage<TERMS>(sb + SB, Ah, Al, Bh, Bl, rowBase, colBase, 64, K, tid);

    const int warp = tid >> 5, lane = tid & 31;
    const int wM = (warp & 3) * 32;
    const int wN = (warp >> 2) * 64;

    float acc[2][8][4];
    #pragma unroll
    for (int mt = 0; mt < 2; mt++)
        #pragma unroll
        for (int n = 0; n < 8; n++)
            #pragma unroll
            for (int j = 0; j < 4; j++) acc[mt][n][j] = 0.f;

    const int aRowOff = (lane & 7) + (lane & 8);
    const int aChOff  = (lane >> 4) & 1;
    const int bRowOff = (lane & 7) + ((lane & 16) >> 1);
    const int bChOff  = (lane >> 3) & 1;

    for (int it = 0; it < T; it++) {
        if (it < T - 1) cp_wait1(); else cp_wait0();
        __syncthreads();
        if (it + 2 < T)
            ld_stage<TERMS>(sb + ((it + 2) % 3) * SB, Ah, Al, Bh, Bl,
                            rowBase, colBase, (it + 2) << 6, K, tid);

        const uint32_t stA = sb + (it % 3) * SB;
        const uint32_t stB = stA + AB;

        #pragma unroll
        for (int kk = 0; kk < 4; kk++) {
            uint32_t aH[2][4], aL[2][4];
            #pragma unroll
            for (int mt = 0; mt < 2; mt++) {
                const int r  = wM + mt * 16 + aRowOff;
                const int ch = 2 * kk + aChOff;
                const uint32_t off = r * 128 + ((ch ^ (r & 7)) << 4);
                ldmx4(aH[mt][0], aH[mt][1], aH[mt][2], aH[mt][3], stA + off);
                if (TERMS >= 2)
                    ldmx4(aL[mt][0], aL[mt][1], aL[mt][2], aL[mt][3], stA + 16384 + off);
            }
            #pragma unroll
            for (int nt = 0; nt < 4; nt++) {
                const int r  = wN + nt * 16 + bRowOff;
                const int ch = 2 * kk + bChOff;
                const uint32_t off = r * 128 + ((ch ^ (r & 7)) << 4);
                uint32_t h0, h1, h2, h3;
                ldmx4(h0, h1, h2, h3, stB + off);
                #pragma unroll
                for (int mt = 0; mt < 2; mt++) {
                    mma16816(acc[mt][nt * 2],     aH[mt], h0, h1);
                    mma16816(acc[mt][nt * 2 + 1], aH[mt], h2, h3);
                    if (TERMS >= 2) {
                        mma16816(acc[mt][nt * 2],     aL[mt], h0, h1);
                        mma16816(acc[mt][nt * 2 + 1], aL[mt], h2, h3);
                    }
                }
                if (TERMS == 3) {
                    uint32_t l0, l1, l2, l3;
                    ldmx4(l0, l1, l2, l3, stB + 16384 + off);
                    #pragma unroll
                    for (int mt = 0; mt < 2; mt++) {
                        mma16816(acc[mt][nt * 2],     aH[mt], l0, l1);
                        mma16816(acc[mt][nt * 2 + 1], aH[mt], l2, l3);
                    }
                }
            }
        }
    }

    // ---------------- epilogue ----------------
    const int g  = lane >> 2;
    const int t4 = lane & 3;
    #pragma unroll
    for (int mt = 0; mt < 2; mt++) {
        const int row0 = rowBase + wM + mt * 16 + g;
        #pragma unroll
        for (int n = 0; n < 8; n++) {
            const int col = colBase + wN + n * 8 + t4 * 2;
            *(float2*)(Cf + (size_t)row0 * N + col) =
                make_float2(acc[mt][n][0], acc[mt][n][1]);
            *(float2*)(Cf + (size_t)(row0 + 8) * N + col) =
                make_float2(acc[mt][n][2], acc[mt][n][3]);
            if (SPLITOUT == 4) {
                #pragma unroll
                for (int hrow = 0; hrow < 2; hrow++) {
                    const size_t o = (size_t)(row0 + hrow * 8) * N + col;
                    *(__half2*)(Ch + o) = __halves2half2(
                        __float2half(acc[mt][n][hrow * 2]),
                        __float2half(acc[mt][n][hrow * 2 + 1]));
                }
            }
        }
    }
}

// ---------------- fp32 -> (hi,lo) fp16 split ----------------
__global__ __launch_bounds__(256) void split_rm(const float* __restrict__ X,
                                                __half* __restrict__ H, __half* __restrict__ L, int n4)
{
    int i = blockIdx.x * 256 + threadIdx.x;
    if (i >= n4) return;
    float4 v = ((const float4*)X)[i];
    float vs[4] = {v.x, v.y, v.z, v.w};
    __half h[4], l[4];
    #pragma unroll
    for (int j = 0; j < 4; j++) {
        h[j] = __float2half(vs[j]);
        l[j] = __float2half(vs[j] - __half2float(h[j]));
    }
    ((__half2*)H)[2 * i]     = __halves2half2(h[0], h[1]);
    ((__half2*)H)[2 * i + 1] = __halves2half2(h[2], h[3]);
    ((__half2*)L)[2 * i]     = __halves2half2(l[0], l[1]);
    ((__half2*)L)[2 * i + 1] = __halves2half2(l[2], l[3]);
}

// ---------------- fp32 [R,C] -> transposed fp16 [C,R]; L optional ----------------
__global__ __launch_bounds__(256) void tsplit(const float* __restrict__ X,
                                              __half* __restrict__ H, __half* __restrict__ L, int R, int C)
{
    __shared__ float tile[32][33];
    const int tx = threadIdx.x, ty = threadIdx.y;
    const int c0 = blockIdx.x * 32, r0 = blockIdx.y * 32;
    #pragma unroll
    for (int i = 0; i < 32; i += 8)
        tile[ty + i][tx] = X[(size_t)(r0 + ty + i) * C + c0 + tx];
    __syncthreads();
    #pragma unroll
    for (int i = 0; i < 32; i += 8) {
        float v = tile[tx][ty + i];
        __half h = __float2half(v);
        size_t o = (size_t)(c0 + ty + i) * R + r0 + tx;
        H[o] = h;
        if (L) L[o] = __float2half(v - __half2float(h));
    }
}

// ---------------- fused: causal softmax + exact recompute + sparse ctx gather ----------------
// Approx scores (abs err ~<2). Entries within MARGIN of row max are recomputed
// exactly (fp32 dot(qf_i, e_j)). All weight mass above e^-MARGIN lives in the
// candidate set, so ctx_i = sum_cand p_j * e_j computed here in fp32; dropped
// tail mass <= N*e^-MARGIN ~ 8e-6.
#define RC_MARGIN 20.0f
#define RC_CAP 1024
__global__ __launch_bounds__(256) void softmax_ctx(const float* __restrict__ S,
                                                   const float* __restrict__ qf,
                                                   const float* __restrict__ emb,
                                                   __half* __restrict__ cth)
{
    __shared__ float buf[N_CTX];
    __shared__ float red[256];
    __shared__ int   list[RC_CAP];
    __shared__ float pw[RC_CAP];
    __shared__ int   cnt;
    const int i = blockIdx.x, t = threadIdx.x;
    const int n = i + 1;
    const float* row = S + (size_t)i * N_CTX;

    // approx max
    float m = -3.0e38f;
    for (int j = t; j < n; j += 256) { float v = row[j]; buf[j] = v; m = fmaxf(m, v); }
    red[t] = m;
    if (t == 0) cnt = 0;
    __syncthreads();
    for (int s2 = 128; s2 > 0; s2 >>= 1) {
        if (t < s2) red[t] = fmaxf(red[t], red[t + s2]);
        __syncthreads();
    }
    m = red[0];
    __syncthreads();

    // candidate set
    for (int j = t; j < n; j += 256)
        if (buf[j] > m - RC_MARGIN) {
            int p = atomicAdd(&cnt, 1);
            if (p < RC_CAP) list[p] = j;
        }
    __syncthreads();
    const int nc = min(cnt, RC_CAP);

    // exact recompute, one warp per candidate
    const int warp = t >> 5, lane = t & 31;
    const float4* qp = (const float4*)(qf + (size_t)i * D_MODEL);
    for (int c = warp; c < nc; c += 8) {
        const int j = list[c];
        const float4* ep = (const float4*)(emb + (size_t)j * D_MODEL);
        float s = 0.f;
        #pragma unroll 4
        for (int k = lane; k < D_MODEL / 4; k += 32) {
            float4 a = qp[k], b = ep[k];
            s += a.x * b.x + a.y * b.y + a.z * b.z + a.w * b.w;
        }
        #pragma unroll
        for (int off = 16; off > 0; off >>= 1) s += __shfl_xor_sync(0xFFFFFFFFu, s, off);
        if (lane == 0) buf[j] = s;
    }
    __syncthreads();

    // exact max
    m = -3.0e38f;
    for (int j = t; j < n; j += 256) m = fmaxf(m, buf[j]);
    red[t] = m;
    __syncthreads();
    for (int s2 = 128; s2 > 0; s2 >>= 1) {
        if (t < s2) red[t] = fmaxf(red[t], red[t + s2]);
        __syncthreads();
    }
    m = red[0];
    __syncthreads();

    // denominator over full row
    float s = 0.f;
    for (int j = t; j < n; j += 256) s += expf(buf[j] - m);
    red[t] = s;
    __syncthreads();
    for (int s2 = 128; s2 > 0; s2 >>= 1) {
        if (t < s2) red[t] += red[t + s2];
        __syncthreads();
    }
    const float inv = 1.0f / red[0];

    // candidate weights
    for (int c = t; c < nc; c += 256) pw[c] = expf(buf[list[c]] - m) * inv;
    __syncthreads();

    // ctx_i = sum_cand p_j * e_j ; thread t owns cols [8t, 8t+8)
    float acc[8];
    #pragma unroll
    for (int k = 0; k < 8; k++) acc[k] = 0.f;
    for (int c = 0; c < nc; c++) {
        const float p = pw[c];
        const float4* ep = (const float4*)(emb + (size_t)list[c] * D_MODEL + t * 8);
        float4 a = ep[0], b = ep[1];
        acc[0] += p * a.x; acc[1] += p * a.y; acc[2] += p * a.z; acc[3] += p * a.w;
        acc[4] += p * b.x; acc[5] += p * b.y; acc[6] += p * b.z; acc[7] += p * b.w;
    }
    __half2* dst = (__half2*)(cth + (size_t)i * D_MODEL + t * 8);
    #pragma unroll
    for (int k = 0; k < 4; k++)
        dst[k] = __halves2half2(__float2half(acc[2 * k]), __float2half(acc[2 * k + 1]));
}

// ---------------------------------------------------------------------------
extern "C" void kernel_launch(void* const* d_in, const int* in_sizes, int n_in,
                              void* d_out, int out_size)
{
    const float* emb = (const float*)d_in[0];   // [4096, 2048]
    const float* qk  = (const float*)d_in[1];   // [2048, 2048]
    const float* ov  = (const float*)d_in[2];   // [2048, 2048]
    float* out = (float*)d_out;                 // [4096, 2048]

    __half *Eh, *El, *QKTh, *QKTl, *OVTh, *qh, *cth;
    float *scores, *qf;
    cudaGetSymbolAddress((void**)&Eh, g_Eh);     cudaGetSymbolAddress((void**)&El, g_El);
    cudaGetSymbolAddress((void**)&QKTh, g_QKTh); cudaGetSymbolAddress((void**)&QKTl, g_QKTl);
    cudaGetSymbolAddress((void**)&OVTh, g_OVTh);
    cudaGetSymbolAddress((void**)&qh, g_qh);
    cudaGetSymbolAddress((void**)&cth, g_cth);
    cudaGetSymbolAddress((void**)&scores, g_scores);
    cudaGetSymbolAddress((void**)&qf, g_qf);

    const int SMEM3 = 3 * 65536 + 128;
    const int SMEM1 = 3 * 32768 + 128;
    cudaFuncSetAttribute(gemm_hmma<0,4,3>, cudaFuncAttributeMaxDynamicSharedMemorySize, SMEM3);
    cudaFuncSetAttribute(gemm_hmma<1,0,1>, cudaFuncAttributeMaxDynamicSharedMemorySize, SMEM1);
    cudaFuncSetAttribute(gemm_hmma<0,0,1>, cudaFuncAttributeMaxDynamicSharedMemorySize, SMEM1);

    // operand prep
    split_rm<<<(N_CTX * D_MODEL / 4 + 255) / 256, 256>>>(emb, Eh, El, N_CTX * D_MODEL / 4);
    tsplit<<<dim3(D_MODEL / 32, D_MODEL / 32), dim3(32, 8)>>>(qk, QKTh, QKTl, D_MODEL, D_MODEL);
    tsplit<<<dim3(D_MODEL / 32, D_MODEL / 32), dim3(32, 8)>>>(ov, OVTh, nullptr, D_MODEL, D_MODEL);

    // 1) q = E @ QK : 3-term, fp32 + hi fp16 out
    gemm_hmma<0,4,3><<<dim3(D_MODEL / 128, N_CTX / 128), 256, SMEM3>>>(
        Eh, El, QKTh, QKTl, qf, qh, D_MODEL, D_MODEL);
    // 2) scores ~= q @ E^T : 1-term approx, causal tile-skip
    gemm_hmma<1,0,1><<<dim3(N_CTX / 128, N_CTX / 128), 256, SMEM1>>>(
        qh, nullptr, Eh, nullptr, scores, nullptr, N_CTX, D_MODEL);
    // 3) fused softmax + exact recompute + sparse ctx gather -> cth fp16
    softmax_ctx<<<N_CTX, 256>>>(scores, qf, emb, cth);
    // 4) out = ctx @ OV : 1-term, fp32 out
    gemm_hmma<0,0,1><<<dim3(D_MODEL / 128, N_CTX / 128), 256, SMEM1>>>(
        cth, nullptr, OVTh, nullptr, out, nullptr, D_MODEL, D_MODEL);
}

// round 10
// speedup vs baseline: 5.6278x; 1.0037x over previous
#include <cuda_runtime.h>
#include <cuda_fp16.h>
#include <cstdint>
#include <cstddef>

#define N_CTX 4096
#define D_MODEL 2048

// ---------------- scratch (__device__ globals; allocation-free) ----------------
__device__ __half g_Eh [(size_t)N_CTX * D_MODEL], g_El [(size_t)N_CTX * D_MODEL];
__device__ __half g_QKTh[(size_t)D_MODEL * D_MODEL], g_QKTl[(size_t)D_MODEL * D_MODEL];
__device__ __half g_OVTh[(size_t)D_MODEL * D_MODEL];
__device__ __half g_qh [(size_t)N_CTX * D_MODEL];
__device__ float  g_qf [(size_t)N_CTX * D_MODEL];
__device__ float  g_scores[(size_t)N_CTX * N_CTX];
__device__ __half g_cth[(size_t)N_CTX * D_MODEL];

// ---------------- PTX helpers (baseline ISA; no tcgen05) ----------------
__device__ __forceinline__ uint32_t s2u(const void* p) {
    uint32_t a;
    asm("{ .reg .u64 t; cvta.to.shared.u64 t, %1; cvt.u32.u64 %0, t; }" : "=r"(a) : "l"(p));
    return a;
}
__device__ __forceinline__ void cp16(uint32_t d, const void* s) {
    asm volatile("cp.async.cg.shared.global [%0], [%1], 16;" :: "r"(d), "l"(s) : "memory");
}
__device__ __forceinline__ void cp_commit() { asm volatile("cp.async.commit_group;" ::: "memory"); }
__device__ __forceinline__ void cp_wait1()  { asm volatile("cp.async.wait_group 1;" ::: "memory"); }
__device__ __forceinline__ void cp_wait0()  { asm volatile("cp.async.wait_group 0;" ::: "memory"); }
__device__ __forceinline__ void ldmx4(uint32_t& r0, uint32_t& r1, uint32_t& r2, uint32_t& r3, uint32_t a) {
    asm volatile("ldmatrix.sync.aligned.m8n8.x4.shared.b16 {%0,%1,%2,%3}, [%4];"
                 : "=r"(r0), "=r"(r1), "=r"(r2), "=r"(r3) : "r"(a));
}
__device__ __forceinline__ void mma16816(float* c, const uint32_t* a, uint32_t b0, uint32_t b1) {
    asm volatile(
        "mma.sync.aligned.m16n8k16.row.col.f32.f16.f16.f32 "
        "{%0,%1,%2,%3}, {%4,%5,%6,%7}, {%8,%9}, {%0,%1,%2,%3};"
        : "+f"(c[0]), "+f"(c[1]), "+f"(c[2]), "+f"(c[3])
        : "r"(a[0]), "r"(a[1]), "r"(a[2]), "r"(a[3]), "r"(b0), "r"(b1));
}

// ---------------- tile loader: 128 rows x 64 halves, XOR-swizzled 128B rows ----------------
__device__ __forceinline__ void ld_tile(uint32_t dst, const __half* __restrict__ src,
                                        int row0, int kbase, int K, int tid)
{
    const int r  = tid >> 1;
    const int cb = (tid & 1) * 4;
    const __half* g = src + (size_t)(row0 + r) * K + kbase;
    const uint32_t rowoff = dst + r * 128;
    const int rx = r & 7;
    #pragma unroll
    for (int c = 0; c < 4; c++) {
        const int ch = cb + c;
        cp16(rowoff + ((ch ^ rx) << 4), g + ch * 8);
    }
}

// TERMS==1: {Ah,Bh}  TERMS==3: {Ah,Al,Bh,Bl}
template<int TERMS>
__device__ __forceinline__ void ld_stage(uint32_t st,
    const __half* Ah, const __half* Al, const __half* Bh, const __half* Bl,
    int rowBase, int colBase, int kbase, int K, int tid)
{
    constexpr uint32_t AB = (TERMS >= 2) ? 32768u : 16384u;
    ld_tile(st, Ah, rowBase, kbase, K, tid);
    if (TERMS >= 2) ld_tile(st + 16384, Al, rowBase, kbase, K, tid);
    ld_tile(st + AB, Bh, colBase, kbase, K, tid);
    if (TERMS == 3) ld_tile(st + AB + 16384, Bl, colBase, kbase, K, tid);
    cp_commit();
}

// ---------------- split-fp16 HMMA GEMM: C[M,N] = A[M,K] @ B[N,K]^T ----------------
// TERMS: 3 = AhBh+AhBl+AlBh ; 1 = AhBh.
// MODE: 0 dense, 1 causal tile-skip.
// SPLITOUT: 0 fp32 C ; 4 fp32 + hi fp16.
template<int MODE, int SPLITOUT, int TERMS>
__global__ __launch_bounds__(256) void gemm_hmma(
    const __half* __restrict__ Ah, const __half* __restrict__ Al,
    const __half* __restrict__ Bh, const __half* __restrict__ Bl,
    float* __restrict__ Cf, __half* __restrict__ Ch,
    int N, int K)
{
    constexpr uint32_t AB = (TERMS >= 2) ? 32768u : 16384u;
    constexpr uint32_t SB = (TERMS == 3) ? 65536u : 32768u;

    const int rowBase = blockIdx.y * 128;
    const int colBase = blockIdx.x * 128;
    if (MODE == 1 && colBase > rowBase) return;
    const int T = K >> 6;

    extern __shared__ char smraw[];
    const uint32_t sb = (s2u(smraw) + 127) & ~127u;
    const int tid = threadIdx.x;

    ld_stage<TERMS>(sb,      Ah, Al, Bh, Bl, rowBase, colBase, 0,  K, tid);
    ld_stage<TERMS>(sb + SB, Ah, Al, Bh, Bl, rowBase, colBase, 64, K, tid);

    const int warp = tid >> 5, lane = tid & 31;
    const int wM = (warp & 3) * 32;
    const int wN = (warp >> 2) * 64;

    float acc[2][8][4];
    #pragma unroll
    for (int mt = 0; mt < 2; mt++)
        #pragma unroll
        for (int n = 0; n < 8; n++)
            #pragma unroll
            for (int j = 0; j < 4; j++) acc[mt][n][j] = 0.f;

    const int aRowOff = (lane & 7) + (lane & 8);
    const int aChOff  = (lane >> 4) & 1;
    const int bRowOff = (lane & 7) + ((lane & 16) >> 1);
    const int bChOff  = (lane >> 3) & 1;

    for (int it = 0; it < T; it++) {
        if (it < T - 1) cp_wait1(); else cp_wait0();
        __syncthreads();
        if (it + 2 < T)
            ld_stage<TERMS>(sb + ((it + 2) % 3) * SB, Ah, Al, Bh, Bl,
                            rowBase, colBase, (it + 2) << 6, K, tid);

        const uint32_t stA = sb + (it % 3) * SB;
        const uint32_t stB = stA + AB;

        #pragma unroll
        for (int kk = 0; kk < 4; kk++) {
            uint32_t aH[2][4], aL[2][4];
            #pragma unroll
            for (int mt = 0; mt < 2; mt++) {
                const int r  = wM + mt * 16 + aRowOff;
                const int ch = 2 * kk + aChOff;
                const uint32_t off = r * 128 + ((ch ^ (r & 7)) << 4);
                ldmx4(aH[mt][0], aH[mt][1], aH[mt][2], aH[mt][3], stA + off);
                if (TERMS >= 2)
                    ldmx4(aL[mt][0], aL[mt][1], aL[mt][2], aL[mt][3], stA + 16384 + off);
            }
            #pragma unroll
            for (int nt = 0; nt < 4; nt++) {
                const int r  = wN + nt * 16 + bRowOff;
                const int ch = 2 * kk + bChOff;
                const uint32_t off = r * 128 + ((ch ^ (r & 7)) << 4);
                uint32_t h0, h1, h2, h3;
                ldmx4(h0, h1, h2, h3, stB + off);
                #pragma unroll
                for (int mt = 0; mt < 2; mt++) {
                    mma16816(acc[mt][nt * 2],     aH[mt], h0, h1);
                    mma16816(acc[mt][nt * 2 + 1], aH[mt], h2, h3);
                    if (TERMS >= 2) {
                        mma16816(acc[mt][nt * 2],     aL[mt], h0, h1);
                        mma16816(acc[mt][nt * 2 + 1], aL[mt], h2, h3);
                    }
                }
                if (TERMS == 3) {
                    uint32_t l0, l1, l2, l3;
                    ldmx4(l0, l1, l2, l3, stB + 16384 + off);
                    #pragma unroll
                    for (int mt = 0; mt < 2; mt++) {
                        mma16816(acc[mt][nt * 2],     aH[mt], l0, l1);
                        mma16816(acc[mt][nt * 2 + 1], aH[mt], l2, l3);
                    }
                }
            }
        }
    }

    // ---------------- epilogue ----------------
    const int g  = lane >> 2;
    const int t4 = lane & 3;
    #pragma unroll
    for (int mt = 0; mt < 2; mt++) {
        const int row0 = rowBase + wM + mt * 16 + g;
        #pragma unroll
        for (int n = 0; n < 8; n++) {
            const int col = colBase + wN + n * 8 + t4 * 2;
            *(float2*)(Cf + (size_t)row0 * N + col) =
                make_float2(acc[mt][n][0], acc[mt][n][1]);
            *(float2*)(Cf + (size_t)(row0 + 8) * N + col) =
                make_float2(acc[mt][n][2], acc[mt][n][3]);
            if (SPLITOUT == 4) {
                #pragma unroll
                for (int hrow = 0; hrow < 2; hrow++) {
                    const size_t o = (size_t)(row0 + hrow * 8) * N + col;
                    *(__half2*)(Ch + o) = __halves2half2(
                        __float2half(acc[mt][n][hrow * 2]),
                        __float2half(acc[mt][n][hrow * 2 + 1]));
                }
            }
        }
    }
}

// ---------------- fp32 -> (hi,lo) fp16 split ----------------
__global__ __launch_bounds__(256) void split_rm(const float* __restrict__ X,
                                                __half* __restrict__ H, __half* __restrict__ L, int n4)
{
    int i = blockIdx.x * 256 + threadIdx.x;
    if (i >= n4) return;
    float4 v = ((const float4*)X)[i];
    float vs[4] = {v.x, v.y, v.z, v.w};
    __half h[4], l[4];
    #pragma unroll
    for (int j = 0; j < 4; j++) {
        h[j] = __float2half(vs[j]);
        l[j] = __float2half(vs[j] - __half2float(h[j]));
    }
    ((__half2*)H)[2 * i]     = __halves2half2(h[0], h[1]);
    ((__half2*)H)[2 * i + 1] = __halves2half2(h[2], h[3]);
    ((__half2*)L)[2 * i]     = __halves2half2(l[0], l[1]);
    ((__half2*)L)[2 * i + 1] = __halves2half2(l[2], l[3]);
}

// ---------------- fp32 [R,C] -> transposed fp16 [C,R]; L optional ----------------
__global__ __launch_bounds__(256) void tsplit(const float* __restrict__ X,
                                              __half* __restrict__ H, __half* __restrict__ L, int R, int C)
{
    __shared__ float tile[32][33];
    const int tx = threadIdx.x, ty = threadIdx.y;
    const int c0 = blockIdx.x * 32, r0 = blockIdx.y * 32;
    #pragma unroll
    for (int i = 0; i < 32; i += 8)
        tile[ty + i][tx] = X[(size_t)(r0 + ty + i) * C + c0 + tx];
    __syncthreads();
    #pragma unroll
    for (int i = 0; i < 32; i += 8) {
        float v = tile[tx][ty + i];
        __half h = __float2half(v);
        size_t o = (size_t)(c0 + ty + i) * R + r0 + tx;
        H[o] = h;
        if (L) L[o] = __float2half(v - __half2float(h));
    }
}

// ---------------- fused: causal softmax + exact recompute + sparse ctx gather ----------------
// Approx scores (abs err ~<2). Entries within MARGIN of row max are recomputed
// exactly (fp32 dot(qf_i, e_j)). All weight mass above e^-MARGIN lives in the
// candidate set, so ctx_i = sum_cand p_j * e_j computed here in fp32; dropped
// tail mass <= N*e^-MARGIN ~ 8e-6.
#define RC_MARGIN 20.0f
#define RC_CAP 1024
__global__ __launch_bounds__(256) void softmax_ctx(const float* __restrict__ S,
                                                   const float* __restrict__ qf,
                                                   const float* __restrict__ emb,
                                                   __half* __restrict__ cth)
{
    __shared__ float buf[N_CTX];
    __shared__ float red[256];
    __shared__ int   list[RC_CAP];
    __shared__ float pw[RC_CAP];
    __shared__ int   cnt;
    const int i = blockIdx.x, t = threadIdx.x;
    const int n = i + 1;
    const float* row = S + (size_t)i * N_CTX;

    // approx max
    float m = -3.0e38f;
    for (int j = t; j < n; j += 256) { float v = row[j]; buf[j] = v; m = fmaxf(m, v); }
    red[t] = m;
    if (t == 0) cnt = 0;
    __syncthreads();
    for (int s2 = 128; s2 > 0; s2 >>= 1) {
        if (t < s2) red[t] = fmaxf(red[t], red[t + s2]);
        __syncthreads();
    }
    m = red[0];
    __syncthreads();

    // candidate set
    for (int j = t; j < n; j += 256)
        if (buf[j] > m - RC_MARGIN) {
            int p = atomicAdd(&cnt, 1);
            if (p < RC_CAP) list[p] = j;
        }
    __syncthreads();
    const int nc = min(cnt, RC_CAP);

    // exact recompute, one warp per candidate
    const int warp = t >> 5, lane = t & 31;
    const float4* qp = (const float4*)(qf + (size_t)i * D_MODEL);
    for (int c = warp; c < nc; c += 8) {
        const int j = list[c];
        const float4* ep = (const float4*)(emb + (size_t)j * D_MODEL);
        float s = 0.f;
        #pragma unroll 4
        for (int k = lane; k < D_MODEL / 4; k += 32) {
            float4 a = qp[k], b = ep[k];
            s += a.x * b.x + a.y * b.y + a.z * b.z + a.w * b.w;
        }
        #pragma unroll
        for (int off = 16; off > 0; off >>= 1) s += __shfl_xor_sync(0xFFFFFFFFu, s, off);
        if (lane == 0) buf[j] = s;
    }
    __syncthreads();

    // exact max
    m = -3.0e38f;
    for (int j = t; j < n; j += 256) m = fmaxf(m, buf[j]);
    red[t] = m;
    __syncthreads();
    for (int s2 = 128; s2 > 0; s2 >>= 1) {
        if (t < s2) red[t] = fmaxf(red[t], red[t + s2]);
        __syncthreads();
    }
    m = red[0];
    __syncthreads();

    // denominator over full row
    float s = 0.f;
    for (int j = t; j < n; j += 256) s += expf(buf[j] - m);
    red[t] = s;
    __syncthreads();
    for (int s2 = 128; s2 > 0; s2 >>= 1) {
        if (t < s2) red[t] += red[t + s2];
        __syncthreads();
    }
    const float inv = 1.0f / red[0];

    // candidate weights
    for (int c = t; c < nc; c += 256) pw[c] = expf(buf[list[c]] - m) * inv;
    __syncthreads();

    // ctx_i = sum_cand p_j * e_j ; thread t owns cols [8t, 8t+8)
    float acc[8];
    #pragma unroll
    for (int k = 0; k < 8; k++) acc[k] = 0.f;
    for (int c = 0; c < nc; c++) {
        const float p = pw[c];
        const float4* ep = (const float4*)(emb + (size_t)list[c] * D_MODEL + t * 8);
        float4 a = ep[0], b = ep[1];
        acc[0] += p * a.x; acc[1] += p * a.y; acc[2] += p * a.z; acc[3] += p * a.w;
        acc[4] += p * b.x; acc[5] += p * b.y; acc[6] += p * b.z; acc[7] += p * b.w;
    }
    __half2* dst = (__half2*)(cth + (size_t)i * D_MODEL + t * 8);
    #pragma unroll
    for (int k = 0; k < 4; k++)
        dst[k] = __halves2half2(__float2half(acc[2 * k]), __float2half(acc[2 * k + 1]));
}

// ---------------------------------------------------------------------------
extern "C" void kernel_launch(void* const* d_in, const int* in_sizes, int n_in,
                              void* d_out, int out_size)
{
    const float* emb = (const float*)d_in[0];   // [4096, 2048]
    const float* qk  = (const float*)d_in[1];   // [2048, 2048]
    const float* ov  = (const float*)d_in[2];   // [2048, 2048]
    float* out = (float*)d_out;                 // [4096, 2048]

    __half *Eh, *El, *QKTh, *QKTl, *OVTh, *qh, *cth;
    float *scores, *qf;
    cudaGetSymbolAddress((void**)&Eh, g_Eh);     cudaGetSymbolAddress((void**)&El, g_El);
    cudaGetSymbolAddress((void**)&QKTh, g_QKTh); cudaGetSymbolAddress((void**)&QKTl, g_QKTl);
    cudaGetSymbolAddress((void**)&OVTh, g_OVTh);
    cudaGetSymbolAddress((void**)&qh, g_qh);
    cudaGetSymbolAddress((void**)&cth, g_cth);
    cudaGetSymbolAddress((void**)&scores, g_scores);
    cudaGetSymbolAddress((void**)&qf, g_qf);

    const int SMEM3 = 3 * 65536 + 128;
    const int SMEM1 = 3 * 32768 + 128;
    cudaFuncSetAttribute(gemm_hmma<0,4,3>, cudaFuncAttributeMaxDynamicSharedMemorySize, SMEM3);
    cudaFuncSetAttribute(gemm_hmma<1,0,1>, cudaFuncAttributeMaxDynamicSharedMemorySize, SMEM1);
    cudaFuncSetAttribute(gemm_hmma<0,0,1>, cudaFuncAttributeMaxDynamicSharedMemorySize, SMEM1);

    // operand prep
    split_rm<<<(N_CTX * D_MODEL / 4 + 255) / 256, 256>>>(emb, Eh, El, N_CTX * D_MODEL / 4);
    tsplit<<<dim3(D_MODEL / 32, D_MODEL / 32), dim3(32, 8)>>>(qk, QKTh, QKTl, D_MODEL, D_MODEL);
    tsplit<<<dim3(D_MODEL / 32, D_MODEL / 32), dim3(32, 8)>>>(ov, OVTh, nullptr, D_MODEL, D_MODEL);

    // 1) q = E @ QK : 3-term, fp32 + hi fp16 out
    gemm_hmma<0,4,3><<<dim3(D_MODEL / 128, N_CTX / 128), 256, SMEM3>>>(
        Eh, El, QKTh, QKTl, qf, qh, D_MODEL, D_MODEL);
    // 2) scores ~= q @ E^T : 1-term approx, causal tile-skip
    gemm_hmma<1,0,1><<<dim3(N_CTX / 128, N_CTX / 128), 256, SMEM1>>>(
        qh, nullptr, Eh, nullptr, scores, nullptr, N_CTX, D_MODEL);
    // 3) fused softmax + exact recompute + sparse ctx gather -> cth fp16
    softmax_ctx<<<N_CTX, 256>>>(scores, qf, emb, cth);
    // 4) out = ctx @ OV : 1-term, fp32 out
    gemm_hmma<0,0,1><<<dim3(D_MODEL / 128, N_CTX / 128), 256, SMEM1>>>(
        cth, nullptr, OVTh, nullptr, out, nullptr, D_MODEL, D_MODEL);
}